// round 4
// baseline (speedup 1.0000x reference)
#include <cuda_runtime.h>

#define KN   4096
#define LN   128
#define MEM  128
#define G4   512
#define NBLK 128   /* KN / 32 arrays per block */

// ---------------- device scratch (no allocs allowed) ----------------
__device__ float d_Xt[LN * KN];     // normalized numbers, transposed [t][array]  (2 MB)
__device__ float d_Wt[MEM * G4];    // W_hh transposed: [j][g]                    (256 KB)
__device__ float d_Wft[MEM * MEM];  // W_fh transposed: [j][k]
__device__ float d_u[G4];           // W_ih[:,128:] @ w_num
__device__ float d_v[G4];           // W_ih[:,128:] @ b_num + b_ih + b_hh
__device__ float d_tabm[100];       // per-element mean for first 100 flat elems
__device__ float d_tabi[100];       // per-element 1/std (or 1.0)
__device__ float d_gm, d_gi;        // frozen stats at cap=100
__device__ float d_fcp[NBLK * MEM]; // partial sum of sigmoid(f)*c
__device__ float d_hsp[NBLK * MEM]; // partial sum of h

typedef unsigned long long ull;

__device__ __forceinline__ ull pk(float x, float y) {
    ull r; asm("mov.b64 %0, {%1, %2};" : "=l"(r) : "f"(x), "f"(y)); return r;
}
__device__ __forceinline__ void up(ull v, float& x, float& y) {
    asm("mov.b64 {%0, %1}, %2;" : "=f"(x), "=f"(y) : "l"(v));
}
__device__ __forceinline__ ull fma2(ull a, ull b, ull c) {
    ull d; asm("fma.rn.f32x2 %0, %1, %2, %3;" : "=l"(d) : "l"(a), "l"(b), "l"(c)); return d;
}
__device__ __forceinline__ float frcp(float x) {
    float r; asm("rcp.approx.f32 %0, %1;" : "=f"(r) : "f"(x)); return r;
}
__device__ __forceinline__ float sigf(float x) {
    return frcp(1.0f + __expf(-x));
}
__device__ __forceinline__ float tanh_(float x) {
    float ax = fabsf(x);
    float e  = __expf(-2.0f * ax);
    float r  = (1.0f - e) * frcp(1.0f + e);
    return copysignf(r, x);
}

// -------- 1) running stats over the first 100 flattened numbers --------
__global__ void k_stats(const float* __restrict__ nums) {
    if (threadIdx.x == 0 && blockIdx.x == 0) {
        float cs = 0.0f, css = 0.0f;
        for (int i = 0; i < 100; i++) {
            float x = nums[i];
            cs  += x;
            css += x * x;
            float cap  = (float)(i + 1);
            float mean = cs / cap;
            float var  = fmaxf(css / cap - mean * mean, 0.0f);
            float sd   = sqrtf(var);
            bool  use  = (cap > 3.0f) && (sd > 1e-8f);
            float inv  = use ? (1.0f / sd) : 1.0f;
            d_tabm[i] = mean;
            d_tabi[i] = inv;
            if (i == 99) { d_gm = mean; d_gi = inv; }
        }
    }
}

// -------- 2) normalize + transpose into d_Xt[t][array] --------
__global__ void k_norm(const float* __restrict__ nums) {
    int idx = blockIdx.x * blockDim.x + threadIdx.x;
    if (idx >= KN * LN) return;
    float x = nums[idx];
    float m, inv;
    if (idx < 100) { m = d_tabm[idx]; inv = d_tabi[idx]; }
    else           { m = d_gm;        inv = d_gi;        }
    int arr = idx >> 7;        // / LN
    int t   = idx & 127;       // % LN
    d_Xt[t * KN + arr] = (x - m) * inv;
}

// -------- 3) weight prep: transposes + rank-1 input folding --------
__global__ void k_prep(const float* __restrict__ Wih, const float* __restrict__ Whh,
                       const float* __restrict__ bih, const float* __restrict__ bhh,
                       const float* __restrict__ Wfh, const float* __restrict__ wnum,
                       const float* __restrict__ bnum) {
    int idx = blockIdx.x * blockDim.x + threadIdx.x;
    if (idx < G4 * MEM) {                       // transpose W_hh -> [j][g]
        int g = idx >> 7, j = idx & 127;
        d_Wt[j * G4 + g] = Whh[idx];
    }
    int i2 = idx - G4 * MEM;
    if (i2 >= 0 && i2 < MEM * MEM) {            // transpose W_fh -> [j][k]
        int kk = i2 >> 7, j = i2 & 127;
        d_Wft[j * MEM + kk] = Wfh[i2];
    }
    int i3 = idx - G4 * MEM - MEM * MEM;
    if (i3 >= 0 && i3 < G4) {                   // u, v vectors
        const float* row = Wih + i3 * 256 + 128;
        float u = 0.0f, v = 0.0f;
        #pragma unroll 8
        for (int j = 0; j < 128; j++) { u += row[j] * wnum[j]; v += row[j] * bnum[j]; }
        d_u[i3] = u;
        d_v[i3] = v + bih[i3] + bhh[i3];
    }
}

// -------- 4) main LSTM: 128 blocks x 32 arrays, f32x2 register-tiled GEMM --------
__global__ void __launch_bounds__(256) k_lstm(const float* __restrict__ bfh) {
    __shared__ ull   hh[32 * 128];     // (h,h) packed, per local array per hidden j (32 KB)
    __shared__ float red[4][128];

    const int t      = threadIdx.x;
    const int gt     = t & 63;         // gate-pair thread: hidden pair k0 = 2*gt
    const int at     = t >> 6;         // array group (0..3), 8 arrays each
    const int k0     = gt * 2;
    const int abase  = at * 8;
    const int gabase = blockIdx.x * 32 + abase;

    for (int i = t; i < 32 * 128; i += 256) hh[i] = 0ull;

    ull u2[4], v2[4];
    #pragma unroll
    for (int i = 0; i < 4; i++) {
        u2[i] = *(const ull*)&d_u[k0 + 128 * i];
        v2[i] = *(const ull*)&d_v[k0 + 128 * i];
    }
    float c0[8], c1[8];
    #pragma unroll
    for (int a = 0; a < 8; a++) { c0[a] = 0.0f; c1[a] = 0.0f; }
    __syncthreads();

    for (int step = 0; step < LN; ++step) {
        ull acc[4][8];
        #pragma unroll
        for (int a = 0; a < 8; a++) {
            float xv = d_Xt[step * KN + gabase + a];
            ull   xp = pk(xv, xv);
            #pragma unroll
            for (int i = 0; i < 4; i++) acc[i][a] = fma2(u2[i], xp, v2[i]);
        }
        // gates += W_hh @ h   (thread: gates {k0,k0+1}+128i, arrays abase..abase+7)
        #pragma unroll 4
        for (int j = 0; j < 128; j++) {
            ull wp[4];
            #pragma unroll
            for (int i = 0; i < 4; i++)
                wp[i] = *(const ull*)&d_Wt[j * G4 + k0 + 128 * i];
            #pragma unroll
            for (int a = 0; a < 8; a++) {
                ull hv = hh[(abase + a) * 128 + j];
                #pragma unroll
                for (int i = 0; i < 4; i++) acc[i][a] = fma2(wp[i], hv, acc[i][a]);
            }
        }
        __syncthreads();   // everyone finished reading old h
        #pragma unroll
        for (int a = 0; a < 8; a++) {
            float i0, i1, f0, f1, g0, g1, o0, o1;
            up(acc[0][a], i0, i1);
            up(acc[1][a], f0, f1);
            up(acc[2][a], g0, g1);
            up(acc[3][a], o0, o1);
            float cc0 = sigf(f0) * c0[a] + sigf(i0) * tanh_(g0);
            float cc1 = sigf(f1) * c1[a] + sigf(i1) * tanh_(g1);
            float h0  = sigf(o0) * tanh_(cc0);
            float h1  = sigf(o1) * tanh_(cc1);
            c0[a] = cc0; c1[a] = cc1;
            ulonglong2 w2; w2.x = pk(h0, h0); w2.y = pk(h1, h1);
            *(ulonglong2*)&hh[(abase + a) * 128 + k0] = w2;   // STS.128, conflict-free
        }
        __syncthreads();   // new h visible
    }

    // -------- fused epilogue: f-gate GEMM + per-block partial reductions --------
    ull af[8];
    {
        ull binit = pk(bfh[k0], bfh[k0 + 1]);
        #pragma unroll
        for (int a = 0; a < 8; a++) af[a] = binit;
    }
    #pragma unroll 4
    for (int j = 0; j < 128; j++) {
        ull wf = *(const ull*)&d_Wft[j * MEM + k0];
        #pragma unroll
        for (int a = 0; a < 8; a++)
            af[a] = fma2(wf, hh[(abase + a) * 128 + j], af[a]);
    }
    float fcs0 = 0.0f, fcs1 = 0.0f, hs0 = 0.0f, hs1 = 0.0f;
    #pragma unroll
    for (int a = 0; a < 8; a++) {
        float x0, x1; up(af[a], x0, x1);
        fcs0 += sigf(x0) * c0[a];
        fcs1 += sigf(x1) * c1[a];
        float h0a, h0b, h1a, h1b;
        up(hh[(abase + a) * 128 + k0],     h0a, h0b);
        up(hh[(abase + a) * 128 + k0 + 1], h1a, h1b);
        hs0 += h0a; hs1 += h1a;
        (void)h0b; (void)h1b;
    }
    red[at][k0] = fcs0; red[at][k0 + 1] = fcs1;
    __syncthreads();
    if (at == 0) {
        d_fcp[blockIdx.x * MEM + k0]     = red[0][k0] + red[1][k0] + red[2][k0] + red[3][k0];
        d_fcp[blockIdx.x * MEM + k0 + 1] = red[0][k0 + 1] + red[1][k0 + 1] + red[2][k0 + 1] + red[3][k0 + 1];
    }
    __syncthreads();
    red[at][k0] = hs0; red[at][k0 + 1] = hs1;
    __syncthreads();
    if (at == 0) {
        d_hsp[blockIdx.x * MEM + k0]     = red[0][k0] + red[1][k0] + red[2][k0] + red[3][k0];
        d_hsp[blockIdx.x * MEM + k0 + 1] = red[0][k0 + 1] + red[1][k0 + 1] + red[2][k0 + 1] + red[3][k0 + 1];
    }
}

// -------- 5) final tree-LSTM root math --------
__global__ void k_final(const float* __restrict__ Wiou, const float* __restrict__ biou,
                        const float* __restrict__ Wlout, const float* __restrict__ blout,
                        float* __restrict__ out) {
    __shared__ float sh_hs[128];
    __shared__ float sh_h[128];
    int k = threadIdx.x;
    float fc = 0.0f, hs = 0.0f;
    for (int b = 0; b < NBLK; b++) {
        fc += d_fcp[b * MEM + k];
        hs += d_hsp[b * MEM + k];
    }
    sh_hs[k] = hs;
    __syncthreads();
    float iv = biou[k], ov = biou[128 + k], uv = biou[256 + k];
    #pragma unroll 8
    for (int j = 0; j < 128; j++) {
        float h = sh_hs[j];
        iv += Wiou[k * 128 + j] * h;
        ov += Wiou[(128 + k) * 128 + j] * h;
        uv += Wiou[(256 + k) * 128 + j] * h;
    }
    float cv = sigf(iv) * tanh_(uv) + fc;
    float hv = sigf(ov) * tanh_(cv);
    out[k]  = cv;
    sh_h[k] = hv;
    __syncthreads();
    float hh_ = blout[k];
    #pragma unroll 8
    for (int j = 0; j < 128; j++) hh_ += Wlout[k * 128 + j] * sh_h[j];
    out[128 + k] = hh_;
}

extern "C" void kernel_launch(void* const* d_in, const int* in_sizes, int n_in,
                              void* d_out, int out_size) {
    const float* numbers = (const float*)d_in[0];
    const float* wnum    = (const float*)d_in[1];
    const float* bnum    = (const float*)d_in[2];
    const float* Wih     = (const float*)d_in[3];
    const float* Whh     = (const float*)d_in[4];
    const float* bih     = (const float*)d_in[5];
    const float* bhh     = (const float*)d_in[6];
    const float* Wfh     = (const float*)d_in[7];
    const float* bfh     = (const float*)d_in[8];
    const float* Wiou    = (const float*)d_in[9];
    const float* biou    = (const float*)d_in[10];
    const float* Wlout   = (const float*)d_in[11];
    const float* blout   = (const float*)d_in[12];
    float* out = (float*)d_out;

    k_stats<<<1, 32>>>(numbers);
    k_norm<<<(KN * LN + 255) / 256, 256>>>(numbers);
    k_prep<<<(G4 * MEM + MEM * MEM + G4 + 255) / 256, 256>>>(Wih, Whh, bih, bhh, Wfh, wnum, bnum);
    k_lstm<<<NBLK, 256>>>(bfh);
    k_final<<<1, 128>>>(Wiou, biou, Wlout, blout, out);
}

// round 5
// speedup vs baseline: 1.0347x; 1.0347x over previous
#include <cuda_runtime.h>

#define KN   4096
#define LN   128
#define MEM  128
#define G4   512
#define NBLK 128   /* KN / 32 arrays per block */

// ---------------- device scratch (no allocs allowed) ----------------
__device__ float d_Xt[LN * KN];     // normalized numbers, transposed [t][array]  (2 MB)
__device__ float d_Wt[MEM * G4];    // W_hh transposed: [j][g]                    (256 KB)
__device__ float d_Wft[MEM * MEM];  // W_fh transposed: [j][k]
__device__ float d_u[G4];           // W_ih[:,128:] @ w_num
__device__ float d_v[G4];           // W_ih[:,128:] @ b_num + b_ih + b_hh
__device__ float d_tabm[100];       // per-element mean for first 100 flat elems
__device__ float d_tabi[100];       // per-element 1/std (or 1.0)
__device__ float d_gm, d_gi;        // frozen stats at cap=100
__device__ float d_fcp[NBLK * MEM]; // partial sum of sigmoid(f)*c
__device__ float d_hsp[NBLK * MEM]; // partial sum of h

typedef unsigned long long ull;

__device__ __forceinline__ ull pk(float x, float y) {
    ull r; asm("mov.b64 %0, {%1, %2};" : "=l"(r) : "f"(x), "f"(y)); return r;
}
__device__ __forceinline__ void up(ull v, float& x, float& y) {
    asm("mov.b64 {%0, %1}, %2;" : "=f"(x), "=f"(y) : "l"(v));
}
__device__ __forceinline__ ull fma2(ull a, ull b, ull c) {
    ull d; asm("fma.rn.f32x2 %0, %1, %2, %3;" : "=l"(d) : "l"(a), "l"(b), "l"(c)); return d;
}
__device__ __forceinline__ float frcp(float x) {
    float r; asm("rcp.approx.f32 %0, %1;" : "=f"(r) : "f"(x)); return r;
}
__device__ __forceinline__ float sigf(float x) {
    return frcp(1.0f + __expf(-x));
}
__device__ __forceinline__ float tanh_(float x) {
    float ax = fabsf(x);
    float e  = __expf(-2.0f * ax);
    float r  = (1.0f - e) * frcp(1.0f + e);
    return copysignf(r, x);
}

// -------- 1) running stats over the first 100 flattened numbers --------
__global__ void k_stats(const float* __restrict__ nums) {
    if (threadIdx.x == 0 && blockIdx.x == 0) {
        float cs = 0.0f, css = 0.0f;
        for (int i = 0; i < 100; i++) {
            float x = nums[i];
            cs  += x;
            css += x * x;
            float cap  = (float)(i + 1);
            float mean = cs / cap;
            float var  = fmaxf(css / cap - mean * mean, 0.0f);
            float sd   = sqrtf(var);
            bool  use  = (cap > 3.0f) && (sd > 1e-8f);
            float inv  = use ? (1.0f / sd) : 1.0f;
            d_tabm[i] = mean;
            d_tabi[i] = inv;
            if (i == 99) { d_gm = mean; d_gi = inv; }
        }
    }
}

// -------- 2) normalize + transpose into d_Xt[t][array] --------
__global__ void k_norm(const float* __restrict__ nums) {
    int idx = blockIdx.x * blockDim.x + threadIdx.x;
    if (idx >= KN * LN) return;
    float x = nums[idx];
    float m, inv;
    if (idx < 100) { m = d_tabm[idx]; inv = d_tabi[idx]; }
    else           { m = d_gm;        inv = d_gi;        }
    int arr = idx >> 7;        // / LN
    int t   = idx & 127;       // % LN
    d_Xt[t * KN + arr] = (x - m) * inv;
}

// -------- 3) weight prep: transposes + rank-1 input folding --------
__global__ void k_prep(const float* __restrict__ Wih, const float* __restrict__ Whh,
                       const float* __restrict__ bih, const float* __restrict__ bhh,
                       const float* __restrict__ Wfh, const float* __restrict__ wnum,
                       const float* __restrict__ bnum) {
    int idx = blockIdx.x * blockDim.x + threadIdx.x;
    if (idx < G4 * MEM) {                       // transpose W_hh -> [j][g]
        int g = idx >> 7, j = idx & 127;
        d_Wt[j * G4 + g] = Whh[idx];
    }
    int i2 = idx - G4 * MEM;
    if (i2 >= 0 && i2 < MEM * MEM) {            // transpose W_fh -> [j][k]
        int kk = i2 >> 7, j = i2 & 127;
        d_Wft[j * MEM + kk] = Wfh[i2];
    }
    int i3 = idx - G4 * MEM - MEM * MEM;
    if (i3 >= 0 && i3 < G4) {                   // u, v vectors
        const float* row = Wih + i3 * 256 + 128;
        float u = 0.0f, v = 0.0f;
        #pragma unroll 8
        for (int j = 0; j < 128; j++) { u += row[j] * wnum[j]; v += row[j] * bnum[j]; }
        d_u[i3] = u;
        d_v[i3] = v + bih[i3] + bhh[i3];
    }
}

// -------- 4) main LSTM: 128 blocks x 512 threads, 4 arrays/thread --------
// thread t: gate-pair thread gt = t & 63 -> hidden pair k0 = 2*gt, all 4 gates
//           array group    at = t >> 6 (0..7) -> 4 arrays abase = 4*at
__global__ void __launch_bounds__(512) k_lstm(const float* __restrict__ bfh) {
    __shared__ ull   hh[32 * 128];     // (h,h) packed: [local array][hidden j] (32 KB)
    __shared__ float red[8][128];

    const int t      = threadIdx.x;
    const int gt     = t & 63;
    const int at     = t >> 6;         // 0..7
    const int k0     = gt * 2;
    const int abase  = at * 4;
    const int gabase = blockIdx.x * 32 + abase;

    for (int i = t; i < 32 * 128; i += 512) hh[i] = 0ull;

    ull u2[4], v2[4];
    #pragma unroll
    for (int i = 0; i < 4; i++) {
        u2[i] = *(const ull*)&d_u[k0 + 128 * i];
        v2[i] = *(const ull*)&d_v[k0 + 128 * i];
    }
    float c0[4], c1[4];
    #pragma unroll
    for (int a = 0; a < 4; a++) { c0[a] = 0.0f; c1[a] = 0.0f; }

    const ull* W64 = (const ull*)d_Wt;   // [j][pair g]: index j*256 + pair
    __syncthreads();

    for (int step = 0; step < LN; ++step) {
        ull acc[4][4];
        {
            float4 xv4 = *(const float4*)&d_Xt[step * KN + gabase];
            float xs[4] = {xv4.x, xv4.y, xv4.z, xv4.w};
            #pragma unroll
            for (int a = 0; a < 4; a++) {
                ull xp = pk(xs[a], xs[a]);
                #pragma unroll
                for (int i = 0; i < 4; i++) acc[i][a] = fma2(u2[i], xp, v2[i]);
            }
        }
        // gates += W_hh @ h ; process j in pairs so hv comes in as LDS.128
        #pragma unroll 2
        for (int j = 0; j < 128; j += 2) {
            ull wpa[4], wpb[4];
            #pragma unroll
            for (int i = 0; i < 4; i++) {
                wpa[i] = W64[j * 256 + gt + 64 * i];
                wpb[i] = W64[(j + 1) * 256 + gt + 64 * i];
            }
            ulonglong2 hv2[4];
            #pragma unroll
            for (int a = 0; a < 4; a++)
                hv2[a] = *(const ulonglong2*)&hh[(abase + a) * 128 + j];
            #pragma unroll
            for (int a = 0; a < 4; a++) {
                #pragma unroll
                for (int i = 0; i < 4; i++) {
                    acc[i][a] = fma2(wpa[i], hv2[a].x, acc[i][a]);
                    acc[i][a] = fma2(wpb[i], hv2[a].y, acc[i][a]);
                }
            }
        }
        __syncthreads();   // everyone finished reading old h
        #pragma unroll
        for (int a = 0; a < 4; a++) {
            float i0, i1, f0, f1, g0, g1, o0, o1;
            up(acc[0][a], i0, i1);
            up(acc[1][a], f0, f1);
            up(acc[2][a], g0, g1);
            up(acc[3][a], o0, o1);
            float cc0 = sigf(f0) * c0[a] + sigf(i0) * tanh_(g0);
            float cc1 = sigf(f1) * c1[a] + sigf(i1) * tanh_(g1);
            float h0  = sigf(o0) * tanh_(cc0);
            float h1  = sigf(o1) * tanh_(cc1);
            c0[a] = cc0; c1[a] = cc1;
            ulonglong2 w2; w2.x = pk(h0, h0); w2.y = pk(h1, h1);
            *(ulonglong2*)&hh[(abase + a) * 128 + k0] = w2;   // STS.128, coalesced
        }
        __syncthreads();   // new h visible
    }

    // -------- fused epilogue: f-gate GEMM + per-block partial reductions --------
    ull af[4];
    {
        ull binit = pk(bfh[k0], bfh[k0 + 1]);
        #pragma unroll
        for (int a = 0; a < 4; a++) af[a] = binit;
    }
    #pragma unroll 2
    for (int j = 0; j < 128; j += 2) {
        ull wfa = *(const ull*)&d_Wft[j * MEM + k0];
        ull wfb = *(const ull*)&d_Wft[(j + 1) * MEM + k0];
        #pragma unroll
        for (int a = 0; a < 4; a++) {
            ulonglong2 hv2 = *(const ulonglong2*)&hh[(abase + a) * 128 + j];
            af[a] = fma2(wfa, hv2.x, af[a]);
            af[a] = fma2(wfb, hv2.y, af[a]);
        }
    }
    float fcs0 = 0.0f, fcs1 = 0.0f, hs0 = 0.0f, hs1 = 0.0f;
    #pragma unroll
    for (int a = 0; a < 4; a++) {
        float x0, x1; up(af[a], x0, x1);
        fcs0 += sigf(x0) * c0[a];
        fcs1 += sigf(x1) * c1[a];
        float h0a, h0b, h1a, h1b;
        up(hh[(abase + a) * 128 + k0],     h0a, h0b);
        up(hh[(abase + a) * 128 + k0 + 1], h1a, h1b);
        hs0 += h0a; hs1 += h1a;
        (void)h0b; (void)h1b;
    }
    red[at][k0] = fcs0; red[at][k0 + 1] = fcs1;
    __syncthreads();
    if (at == 0) {
        float s0 = 0.0f, s1 = 0.0f;
        #pragma unroll
        for (int g = 0; g < 8; g++) { s0 += red[g][k0]; s1 += red[g][k0 + 1]; }
        d_fcp[blockIdx.x * MEM + k0]     = s0;
        d_fcp[blockIdx.x * MEM + k0 + 1] = s1;
    }
    __syncthreads();
    red[at][k0] = hs0; red[at][k0 + 1] = hs1;
    __syncthreads();
    if (at == 0) {
        float s0 = 0.0f, s1 = 0.0f;
        #pragma unroll
        for (int g = 0; g < 8; g++) { s0 += red[g][k0]; s1 += red[g][k0 + 1]; }
        d_hsp[blockIdx.x * MEM + k0]     = s0;
        d_hsp[blockIdx.x * MEM + k0 + 1] = s1;
    }
}

// -------- 5) final tree-LSTM root math --------
__global__ void k_final(const float* __restrict__ Wiou, const float* __restrict__ biou,
                        const float* __restrict__ Wlout, const float* __restrict__ blout,
                        float* __restrict__ out) {
    __shared__ float sh_hs[128];
    __shared__ float sh_h[128];
    int k = threadIdx.x;
    float fc = 0.0f, hs = 0.0f;
    for (int b = 0; b < NBLK; b++) {
        fc += d_fcp[b * MEM + k];
        hs += d_hsp[b * MEM + k];
    }
    sh_hs[k] = hs;
    __syncthreads();
    float iv = biou[k], ov = biou[128 + k], uv = biou[256 + k];
    #pragma unroll 8
    for (int j = 0; j < 128; j++) {
        float h = sh_hs[j];
        iv += Wiou[k * 128 + j] * h;
        ov += Wiou[(128 + k) * 128 + j] * h;
        uv += Wiou[(256 + k) * 128 + j] * h;
    }
    float cv = sigf(iv) * tanh_(uv) + fc;
    float hv = sigf(ov) * tanh_(cv);
    out[k]  = cv;
    sh_h[k] = hv;
    __syncthreads();
    float hh_ = blout[k];
    #pragma unroll 8
    for (int j = 0; j < 128; j++) hh_ += Wlout[k * 128 + j] * sh_h[j];
    out[128 + k] = hh_;
}

extern "C" void kernel_launch(void* const* d_in, const int* in_sizes, int n_in,
                              void* d_out, int out_size) {
    const float* numbers = (const float*)d_in[0];
    const float* wnum    = (const float*)d_in[1];
    const float* bnum    = (const float*)d_in[2];
    const float* Wih     = (const float*)d_in[3];
    const float* Whh     = (const float*)d_in[4];
    const float* bih     = (const float*)d_in[5];
    const float* bhh     = (const float*)d_in[6];
    const float* Wfh     = (const float*)d_in[7];
    const float* bfh     = (const float*)d_in[8];
    const float* Wiou    = (const float*)d_in[9];
    const float* biou    = (const float*)d_in[10];
    const float* Wlout   = (const float*)d_in[11];
    const float* blout   = (const float*)d_in[12];
    float* out = (float*)d_out;

    k_stats<<<1, 32>>>(numbers);
    k_norm<<<(KN * LN + 255) / 256, 256>>>(numbers);
    k_prep<<<(G4 * MEM + MEM * MEM + G4 + 255) / 256, 256>>>(Wih, Whh, bih, bhh, Wfh, wnum, bnum);
    k_lstm<<<NBLK, 512>>>(bfh);
    k_final<<<1, 128>>>(Wiou, biou, Wlout, blout, out);
}

// round 6
// speedup vs baseline: 1.0365x; 1.0018x over previous
#include <cuda_runtime.h>

#define KN   4096
#define LN   128
#define MEM  128
#define G4   512
#define NBLK 128   /* KN / 32 arrays per block */

// ---------------- device scratch (no allocs allowed) ----------------
__device__ float d_Xt[LN * KN];     // normalized numbers, transposed [t][array]  (2 MB)
__device__ float d_Wt[MEM * G4];    // W_hh transposed: [j][g]                    (256 KB)
__device__ float d_Wft[MEM * MEM];  // W_fh transposed: [j][k]
__device__ float d_u[G4];           // W_ih[:,128:] @ w_num
__device__ float d_v[G4];           // W_ih[:,128:] @ b_num + b_ih + b_hh
__device__ float d_tabm[100];       // per-element mean for first 100 flat elems
__device__ float d_tabi[100];       // per-element 1/std (or 1.0)
__device__ float d_gm, d_gi;        // frozen stats at cap=100
__device__ float d_fcp[NBLK * MEM]; // partial sum of sigmoid(f)*c
__device__ float d_hsp[NBLK * MEM]; // partial sum of h

typedef unsigned long long ull;

__device__ __forceinline__ ull pk(float x, float y) {
    ull r; asm("mov.b64 %0, {%1, %2};" : "=l"(r) : "f"(x), "f"(y)); return r;
}
__device__ __forceinline__ void up(ull v, float& x, float& y) {
    asm("mov.b64 {%0, %1}, %2;" : "=f"(x), "=f"(y) : "l"(v));
}
__device__ __forceinline__ ull fma2(ull a, ull b, ull c) {
    ull d; asm("fma.rn.f32x2 %0, %1, %2, %3;" : "=l"(d) : "l"(a), "l"(b), "l"(c)); return d;
}
__device__ __forceinline__ float frcp(float x) {
    float r; asm("rcp.approx.f32 %0, %1;" : "=f"(r) : "f"(x)); return r;
}
__device__ __forceinline__ float sigf(float x) {
    return frcp(1.0f + __expf(-x));
}
__device__ __forceinline__ float tanh_(float x) {
    float ax = fabsf(x);
    float e  = __expf(-2.0f * ax);
    float r  = (1.0f - e) * frcp(1.0f + e);
    return copysignf(r, x);
}

// -------- 1) running stats over the first 100 flattened numbers --------
__global__ void k_stats(const float* __restrict__ nums) {
    if (threadIdx.x == 0 && blockIdx.x == 0) {
        float cs = 0.0f, css = 0.0f;
        for (int i = 0; i < 100; i++) {
            float x = nums[i];
            cs  += x;
            css += x * x;
            float cap  = (float)(i + 1);
            float mean = cs / cap;
            float var  = fmaxf(css / cap - mean * mean, 0.0f);
            float sd   = sqrtf(var);
            bool  use  = (cap > 3.0f) && (sd > 1e-8f);
            float inv  = use ? (1.0f / sd) : 1.0f;
            d_tabm[i] = mean;
            d_tabi[i] = inv;
            if (i == 99) { d_gm = mean; d_gi = inv; }
        }
    }
}

// -------- 2) normalize + transpose into d_Xt[t][array] --------
__global__ void k_norm(const float* __restrict__ nums) {
    int idx = blockIdx.x * blockDim.x + threadIdx.x;
    if (idx >= KN * LN) return;
    float x = nums[idx];
    float m, inv;
    if (idx < 100) { m = d_tabm[idx]; inv = d_tabi[idx]; }
    else           { m = d_gm;        inv = d_gi;        }
    int arr = idx >> 7;        // / LN
    int t   = idx & 127;       // % LN
    d_Xt[t * KN + arr] = (x - m) * inv;
}

// -------- 3) weight prep: transposes + rank-1 input folding --------
__global__ void k_prep(const float* __restrict__ Wih, const float* __restrict__ Whh,
                       const float* __restrict__ bih, const float* __restrict__ bhh,
                       const float* __restrict__ Wfh, const float* __restrict__ wnum,
                       const float* __restrict__ bnum) {
    int idx = blockIdx.x * blockDim.x + threadIdx.x;
    if (idx < G4 * MEM) {                       // transpose W_hh -> [j][g]
        int g = idx >> 7, j = idx & 127;
        d_Wt[j * G4 + g] = Whh[idx];
    }
    int i2 = idx - G4 * MEM;
    if (i2 >= 0 && i2 < MEM * MEM) {            // transpose W_fh -> [j][k]
        int kk = i2 >> 7, j = i2 & 127;
        d_Wft[j * MEM + kk] = Wfh[i2];
    }
    int i3 = idx - G4 * MEM - MEM * MEM;
    if (i3 >= 0 && i3 < G4) {                   // u, v vectors
        const float* row = Wih + i3 * 256 + 128;
        float u = 0.0f, v = 0.0f;
        #pragma unroll 8
        for (int j = 0; j < 128; j++) { u += row[j] * wnum[j]; v += row[j] * bnum[j]; }
        d_u[i3] = u;
        d_v[i3] = v + bih[i3] + bhh[i3];
    }
}

// -------- 4) main LSTM: 128 blocks x 512 threads, 4 arrays/thread --------
// thread t: gate-pair thread gt = t & 63 -> hidden pair k0 = 2*gt, all 4 gates
//           array group    at = t >> 6 (0..7) -> 4 arrays abase = 4*at
__global__ void __launch_bounds__(512) k_lstm(const float* __restrict__ bfh) {
    __shared__ ull   hh[32 * 128];     // (h,h) packed: [local array][hidden j] (32 KB)
    __shared__ float red[8][128];

    const int t      = threadIdx.x;
    const int gt     = t & 63;
    const int at     = t >> 6;         // 0..7
    const int k0     = gt * 2;
    const int abase  = at * 4;
    const int gabase = blockIdx.x * 32 + abase;

    for (int i = t; i < 32 * 128; i += 512) hh[i] = 0ull;

    ull u2[4], v2[4];
    #pragma unroll
    for (int i = 0; i < 4; i++) {
        u2[i] = *(const ull*)&d_u[k0 + 128 * i];
        v2[i] = *(const ull*)&d_v[k0 + 128 * i];
    }
    float c0[4], c1[4];
    #pragma unroll
    for (int a = 0; a < 4; a++) { c0[a] = 0.0f; c1[a] = 0.0f; }

    const ull* W64 = (const ull*)d_Wt;   // [j][pair g]: index j*256 + pair
    __syncthreads();

    for (int step = 0; step < LN; ++step) {
        ull acc[4][4];
        {
            float4 xv4 = *(const float4*)&d_Xt[step * KN + gabase];
            float xs[4] = {xv4.x, xv4.y, xv4.z, xv4.w};
            #pragma unroll
            for (int a = 0; a < 4; a++) {
                ull xp = pk(xs[a], xs[a]);
                #pragma unroll
                for (int i = 0; i < 4; i++) acc[i][a] = fma2(u2[i], xp, v2[i]);
            }
        }
        // gates += W_hh @ h ; process j in pairs so hv comes in as LDS.128
        #pragma unroll 2
        for (int j = 0; j < 128; j += 2) {
            ull wpa[4], wpb[4];
            #pragma unroll
            for (int i = 0; i < 4; i++) {
                wpa[i] = W64[j * 256 + gt + 64 * i];
                wpb[i] = W64[(j + 1) * 256 + gt + 64 * i];
            }
            ulonglong2 hv2[4];
            #pragma unroll
            for (int a = 0; a < 4; a++)
                hv2[a] = *(const ulonglong2*)&hh[(abase + a) * 128 + j];
            #pragma unroll
            for (int a = 0; a < 4; a++) {
                #pragma unroll
                for (int i = 0; i < 4; i++) {
                    acc[i][a] = fma2(wpa[i], hv2[a].x, acc[i][a]);
                    acc[i][a] = fma2(wpb[i], hv2[a].y, acc[i][a]);
                }
            }
        }
        __syncthreads();   // everyone finished reading old h
        #pragma unroll
        for (int a = 0; a < 4; a++) {
            float i0, i1, f0, f1, g0, g1, o0, o1;
            up(acc[0][a], i0, i1);
            up(acc[1][a], f0, f1);
            up(acc[2][a], g0, g1);
            up(acc[3][a], o0, o1);
            float cc0 = sigf(f0) * c0[a] + sigf(i0) * tanh_(g0);
            float cc1 = sigf(f1) * c1[a] + sigf(i1) * tanh_(g1);
            float h0  = sigf(o0) * tanh_(cc0);
            float h1  = sigf(o1) * tanh_(cc1);
            c0[a] = cc0; c1[a] = cc1;
            ulonglong2 w2; w2.x = pk(h0, h0); w2.y = pk(h1, h1);
            *(ulonglong2*)&hh[(abase + a) * 128 + k0] = w2;   // STS.128, coalesced
        }
        __syncthreads();   // new h visible
    }

    // -------- fused epilogue: f-gate GEMM + per-block partial reductions --------
    ull af[4];
    {
        ull binit = pk(bfh[k0], bfh[k0 + 1]);
        #pragma unroll
        for (int a = 0; a < 4; a++) af[a] = binit;
    }
    #pragma unroll 2
    for (int j = 0; j < 128; j += 2) {
        ull wfa = *(const ull*)&d_Wft[j * MEM + k0];
        ull wfb = *(const ull*)&d_Wft[(j + 1) * MEM + k0];
        #pragma unroll
        for (int a = 0; a < 4; a++) {
            ulonglong2 hv2 = *(const ulonglong2*)&hh[(abase + a) * 128 + j];
            af[a] = fma2(wfa, hv2.x, af[a]);
            af[a] = fma2(wfb, hv2.y, af[a]);
        }
    }
    float fcs0 = 0.0f, fcs1 = 0.0f, hs0 = 0.0f, hs1 = 0.0f;
    #pragma unroll
    for (int a = 0; a < 4; a++) {
        float x0, x1; up(af[a], x0, x1);
        fcs0 += sigf(x0) * c0[a];
        fcs1 += sigf(x1) * c1[a];
        float h0a, h0b, h1a, h1b;
        up(hh[(abase + a) * 128 + k0],     h0a, h0b);
        up(hh[(abase + a) * 128 + k0 + 1], h1a, h1b);
        hs0 += h0a; hs1 += h1a;
        (void)h0b; (void)h1b;
    }
    red[at][k0] = fcs0; red[at][k0 + 1] = fcs1;
    __syncthreads();
    if (at == 0) {
        float s0 = 0.0f, s1 = 0.0f;
        #pragma unroll
        for (int g = 0; g < 8; g++) { s0 += red[g][k0]; s1 += red[g][k0 + 1]; }
        d_fcp[blockIdx.x * MEM + k0]     = s0;
        d_fcp[blockIdx.x * MEM + k0 + 1] = s1;
    }
    __syncthreads();
    red[at][k0] = hs0; red[at][k0 + 1] = hs1;
    __syncthreads();
    if (at == 0) {
        float s0 = 0.0f, s1 = 0.0f;
        #pragma unroll
        for (int g = 0; g < 8; g++) { s0 += red[g][k0]; s1 += red[g][k0 + 1]; }
        d_hsp[blockIdx.x * MEM + k0]     = s0;
        d_hsp[blockIdx.x * MEM + k0 + 1] = s1;
    }
}

// -------- 5) final tree-LSTM root math --------
__global__ void k_final(const float* __restrict__ Wiou, const float* __restrict__ biou,
                        const float* __restrict__ Wlout, const float* __restrict__ blout,
                        float* __restrict__ out) {
    __shared__ float sh_hs[128];
    __shared__ float sh_h[128];
    int k = threadIdx.x;
    float fc = 0.0f, hs = 0.0f;
    for (int b = 0; b < NBLK; b++) {
        fc += d_fcp[b * MEM + k];
        hs += d_hsp[b * MEM + k];
    }
    sh_hs[k] = hs;
    __syncthreads();
    float iv = biou[k], ov = biou[128 + k], uv = biou[256 + k];
    #pragma unroll 8
    for (int j = 0; j < 128; j++) {
        float h = sh_hs[j];
        iv += Wiou[k * 128 + j] * h;
        ov += Wiou[(128 + k) * 128 + j] * h;
        uv += Wiou[(256 + k) * 128 + j] * h;
    }
    float cv = sigf(iv) * tanh_(uv) + fc;
    float hv = sigf(ov) * tanh_(cv);
    out[k]  = cv;
    sh_h[k] = hv;
    __syncthreads();
    float hh_ = blout[k];
    #pragma unroll 8
    for (int j = 0; j < 128; j++) hh_ += Wlout[k * 128 + j] * sh_h[j];
    out[128 + k] = hh_;
}

extern "C" void kernel_launch(void* const* d_in, const int* in_sizes, int n_in,
                              void* d_out, int out_size) {
    const float* numbers = (const float*)d_in[0];
    const float* wnum    = (const float*)d_in[1];
    const float* bnum    = (const float*)d_in[2];
    const float* Wih     = (const float*)d_in[3];
    const float* Whh     = (const float*)d_in[4];
    const float* bih     = (const float*)d_in[5];
    const float* bhh     = (const float*)d_in[6];
    const float* Wfh     = (const float*)d_in[7];
    const float* bfh     = (const float*)d_in[8];
    const float* Wiou    = (const float*)d_in[9];
    const float* biou    = (const float*)d_in[10];
    const float* Wlout   = (const float*)d_in[11];
    const float* blout   = (const float*)d_in[12];
    float* out = (float*)d_out;

    k_stats<<<1, 32>>>(numbers);
    k_norm<<<(KN * LN + 255) / 256, 256>>>(numbers);
    k_prep<<<(G4 * MEM + MEM * MEM + G4 + 255) / 256, 256>>>(Wih, Whh, bih, bhh, Wfh, wnum, bnum);
    k_lstm<<<NBLK, 512>>>(bfh);
    k_final<<<1, 128>>>(Wiou, biou, Wlout, blout, out);
}

// round 8
// speedup vs baseline: 4.4901x; 4.3319x over previous
#include <cuda_runtime.h>
#include <cstdint>

#define KN   4096
#define LN   128
#define MEM  128
#define G4   512
#define NBLK 128
#define THR  256           /* 8 warps */

/* dynamic smem layout (bytes) */
#define OFF_W    0          /* 128 KB : W_hh f16 [512 rows][128 k], 256B/row, chunk-swizzled */
#define OFF_WF   131072     /* 32 KB  : W_fh f16 [128][128], same layout */
#define OFF_HHI  163840     /* 10240 B: h_hi f16 [128 j][32 a], 80B row stride */
#define OFF_HLO  174080     /* 10240 B: h_lo */
#define SMEM_TOTAL 184320

/* ---------------- device scratch ---------------- */
__device__ float d_Xt[LN * KN];
__device__ unsigned short d_W16[G4 * MEM];    /* f16(W_hh) row-major [g][j] */
__device__ unsigned short d_Wf16[MEM * MEM];  /* f16(W_fh) */
__device__ float d_u[G4], d_v[G4];
__device__ float d_tabm[100], d_tabi[100], d_gm, d_gi;
__device__ float d_fcp[NBLK * MEM], d_hsp[NBLK * MEM];

/* ---------------- helpers ---------------- */
__device__ __forceinline__ uint32_t smem_u32(const void* p) {
    uint32_t a;
    asm("{ .reg .u64 t; cvta.to.shared.u64 t, %1; cvt.u32.u64 %0, t; }" : "=r"(a) : "l"(p));
    return a;
}
__device__ __forceinline__ float frcp(float x) { float r; asm("rcp.approx.f32 %0, %1;" : "=f"(r) : "f"(x)); return r; }
__device__ __forceinline__ float sigf(float x) { return frcp(1.0f + __expf(-x)); }
__device__ __forceinline__ float tanh_(float x) {
    float ax = fabsf(x);
    float e  = __expf(-2.0f * ax);
    float r  = (1.0f - e) * frcp(1.0f + e);
    return copysignf(r, x);
}
__device__ __forceinline__ unsigned short f16b(float f) {
    unsigned short u; asm("cvt.rn.f16.f32 %0, %1;" : "=h"(u) : "f"(f)); return u;
}
__device__ __forceinline__ float f16rt(float x) {
    unsigned short b; asm("cvt.rn.f16.f32 %0, %1;" : "=h"(b) : "f"(x));
    float r; asm("cvt.f32.f16 %0, %1;" : "=f"(r) : "h"(b));
    return r;
}
__device__ __forceinline__ unsigned f16x2pk(float lo, float hi) {
    unsigned r; asm("cvt.rn.f16x2.f32 %0, %1, %2;" : "=r"(r) : "f"(hi), "f"(lo)); return r;
}
__device__ __forceinline__ void ldsm4(uint32_t& r0, uint32_t& r1, uint32_t& r2, uint32_t& r3, uint32_t a) {
    asm volatile("ldmatrix.sync.aligned.m8n8.x4.shared.b16 {%0,%1,%2,%3}, [%4];"
                 : "=r"(r0), "=r"(r1), "=r"(r2), "=r"(r3) : "r"(a));
}
__device__ __forceinline__ void ldsm4t(uint32_t& r0, uint32_t& r1, uint32_t& r2, uint32_t& r3, uint32_t a) {
    asm volatile("ldmatrix.sync.aligned.m8n8.x4.trans.shared.b16 {%0,%1,%2,%3}, [%4];"
                 : "=r"(r0), "=r"(r1), "=r"(r2), "=r"(r3) : "r"(a));
}
__device__ __forceinline__ void mma_(float* d, const uint32_t* a, const uint32_t* b) {
    asm volatile("mma.sync.aligned.m16n8k16.row.col.f32.f16.f16.f32 "
                 "{%0,%1,%2,%3},{%4,%5,%6,%7},{%8,%9},{%0,%1,%2,%3};"
                 : "+f"(d[0]), "+f"(d[1]), "+f"(d[2]), "+f"(d[3])
                 : "r"(a[0]), "r"(a[1]), "r"(a[2]), "r"(a[3]), "r"(b[0]), "r"(b[1]));
}

/* -------- 1) running stats over first 100 flat numbers -------- */
__global__ void k_stats(const float* __restrict__ nums) {
    if (threadIdx.x == 0 && blockIdx.x == 0) {
        float cs = 0.0f, css = 0.0f;
        for (int i = 0; i < 100; i++) {
            float x = nums[i];
            cs += x; css += x * x;
            float cap = (float)(i + 1);
            float mean = cs / cap;
            float var = fmaxf(css / cap - mean * mean, 0.0f);
            float sd = sqrtf(var);
            bool use = (cap > 3.0f) && (sd > 1e-8f);
            float inv = use ? (1.0f / sd) : 1.0f;
            d_tabm[i] = mean; d_tabi[i] = inv;
            if (i == 99) { d_gm = mean; d_gi = inv; }
        }
    }
}

/* -------- 2) normalize + transpose -------- */
__global__ void k_norm(const float* __restrict__ nums) {
    int idx = blockIdx.x * blockDim.x + threadIdx.x;
    if (idx >= KN * LN) return;
    float x = nums[idx];
    float m, inv;
    if (idx < 100) { m = d_tabm[idx]; inv = d_tabi[idx]; }
    else           { m = d_gm;        inv = d_gi;        }
    int arr = idx >> 7, t = idx & 127;
    d_Xt[t * KN + arr] = (x - m) * inv;
}

/* -------- 3) weight prep: f16 weights + rank-1 input folding -------- */
__global__ void k_prep(const float* __restrict__ Wih, const float* __restrict__ Whh,
                       const float* __restrict__ bih, const float* __restrict__ bhh,
                       const float* __restrict__ Wfh, const float* __restrict__ wnum,
                       const float* __restrict__ bnum) {
    int idx = blockIdx.x * blockDim.x + threadIdx.x;
    if (idx < G4 * MEM) d_W16[idx] = f16b(Whh[idx]);
    int i2 = idx - G4 * MEM;
    if (i2 >= 0 && i2 < MEM * MEM) d_Wf16[i2] = f16b(Wfh[i2]);
    int i3 = idx - G4 * MEM - MEM * MEM;
    if (i3 >= 0 && i3 < G4) {
        const float* row = Wih + i3 * 256 + 128;
        float u = 0.0f, v = 0.0f;
        #pragma unroll 8
        for (int j = 0; j < 128; j++) { u += row[j] * wnum[j]; v += row[j] * bnum[j]; }
        d_u[i3] = u;
        d_v[i3] = v + bih[i3] + bhh[i3];
    }
}

/* -------- 4) main LSTM: mma.sync m16n8k16 recurrent GEMM -------- */
/* warp w owns hidden rows 16w..16w+16 of ALL 4 gate banks -> epilogue in-register. */
__global__ void __launch_bounds__(THR, 1) k_lstm(const float* __restrict__ bfh) {
    extern __shared__ char smem[];
    const uint32_t sb = smem_u32(smem);
    const int tid = threadIdx.x;
    const int lid = tid & 31;
    const int w   = tid >> 5;
    const int lid4 = lid >> 2, lm4 = lid & 3;
    const int rl  = (lid & 7) | (((lid >> 3) & 1) << 3);  /* row-in-16 for ldmatrix lanes */
    const int ch  = lid >> 4;                              /* k-chunk half */
    const int rmod = rl & 7;

    /* W_hh f16 -> smem, 256B rows, 16B-chunk XOR swizzle (chunk ^= row&7) */
    for (int p = tid; p < G4 * 64; p += THR) {
        int row = p >> 6, q = p & 63;
        unsigned val = ((const unsigned*)d_W16)[p];
        int cc = q >> 2, wd = q & 3;
        *(unsigned*)(smem + OFF_W + row * 256 + ((cc ^ (row & 7)) << 4) + wd * 4) = val;
    }
    for (int p = tid; p < MEM * 64; p += THR) {
        int row = p >> 6, q = p & 63;
        unsigned val = ((const unsigned*)d_Wf16)[p];
        int cc = q >> 2, wd = q & 3;
        *(unsigned*)(smem + OFF_WF + row * 256 + ((cc ^ (row & 7)) << 4) + wd * 4) = val;
    }
    /* zero h hi+lo tiles (contiguous 20480 B) */
    for (int p = tid; p < 5120; p += THR)
        *(unsigned*)(smem + OFF_HHI + p * 4) = 0u;
    __syncthreads();

    /* persistent per-thread constants */
    float u8[8], v8[8];   /* [bank*2 + rowhalf] */
    #pragma unroll
    for (int b = 0; b < 4; b++)
        #pragma unroll
        for (int r = 0; r < 2; r++) {
            int k = 16 * w + lid4 + 8 * r;
            u8[b * 2 + r] = d_u[b * 128 + k];
            v8[b * 2 + r] = d_v[b * 128 + k];
        }
    float cst[16], harr[16];
    #pragma unroll
    for (int i = 0; i < 16; i++) { cst[i] = 0.0f; harr[i] = 0.0f; }

    const uint32_t aBase = sb + OFF_W + (uint32_t)(16 * w + rl) * 256;
    const uint32_t hhiB  = sb + OFF_HHI + (uint32_t)rl * 80 + (uint32_t)ch * 16;
    const uint32_t hloB  = sb + OFF_HLO + (uint32_t)rl * 80 + (uint32_t)ch * 16;

    for (int step = 0; step < LN; step++) {
        float acc[16][4];   /* [bank*4 + ntile][pos] */
        #pragma unroll
        for (int i = 0; i < 16; i++)
            #pragma unroll
            for (int p = 0; p < 4; p++) acc[i][p] = 0.0f;

        #pragma unroll 4
        for (int kb = 0; kb < 8; kb++) {
            uint32_t co = (uint32_t)((2 * kb + ch) ^ rmod) << 4;
            uint32_t A[4][4];
            #pragma unroll
            for (int b = 0; b < 4; b++)
                ldsm4(A[b][0], A[b][1], A[b][2], A[b][3], aBase + (uint32_t)b * 32768 + co);
            uint32_t BH[4][2], BL[4][2];
            #pragma unroll
            for (int p = 0; p < 2; p++) {
                uint32_t r0, r1, r2, r3;
                ldsm4t(r0, r1, r2, r3, hhiB + (uint32_t)kb * 1280 + (uint32_t)p * 32);
                BH[2 * p][0] = r0; BH[2 * p][1] = r1; BH[2 * p + 1][0] = r2; BH[2 * p + 1][1] = r3;
                ldsm4t(r0, r1, r2, r3, hloB + (uint32_t)kb * 1280 + (uint32_t)p * 32);
                BL[2 * p][0] = r0; BL[2 * p][1] = r1; BL[2 * p + 1][0] = r2; BL[2 * p + 1][1] = r3;
            }
            #pragma unroll
            for (int b = 0; b < 4; b++)
                #pragma unroll
                for (int nt = 0; nt < 4; nt++) {
                    mma_(acc[b * 4 + nt], A[b], BH[nt]);
                    mma_(acc[b * 4 + nt], A[b], BL[nt]);
                }
        }
        __syncthreads();   /* all warps done reading h */

        /* epilogue: gates -> (c,h), write h hi/lo back */
        const float2* xp = (const float2*)&d_Xt[step * KN + blockIdx.x * 32];
        #pragma unroll
        for (int nt = 0; nt < 4; nt++) {
            float2 xv = __ldg(&xp[4 * nt + lm4]);
            #pragma unroll
            for (int r = 0; r < 2; r++) {
                float hhi[2], hlo[2];
                #pragma unroll
                for (int q = 0; q < 2; q++) {
                    int pos = 2 * r + q;
                    float x = q ? xv.y : xv.x;
                    float gi = acc[0 * 4 + nt][pos] + fmaf(u8[0 + r], x, v8[0 + r]);
                    float gf = acc[1 * 4 + nt][pos] + fmaf(u8[2 + r], x, v8[2 + r]);
                    float gg = acc[2 * 4 + nt][pos] + fmaf(u8[4 + r], x, v8[4 + r]);
                    float go = acc[3 * 4 + nt][pos] + fmaf(u8[6 + r], x, v8[6 + r]);
                    int cell = nt * 4 + pos;
                    float c2 = sigf(gf) * cst[cell] + sigf(gi) * tanh_(gg);
                    float h  = sigf(go) * tanh_(c2);
                    cst[cell] = c2; harr[cell] = h;
                    float hv = f16rt(h);
                    hhi[q] = hv; hlo[q] = h - hv;
                }
                int k = 16 * w + lid4 + 8 * r;
                uint32_t off = (uint32_t)k * 80 + (uint32_t)(8 * nt + 2 * lm4) * 2;
                *(unsigned*)(smem + OFF_HHI + off) = f16x2pk(hhi[0], hhi[1]);
                *(unsigned*)(smem + OFF_HLO + off) = f16x2pk(hlo[0], hlo[1]);
            }
        }
        __syncthreads();   /* new h visible */
    }

    /* -------- fused f-gate GEMM (W_fh @ h) + reductions -------- */
    float fac[4][4];
    #pragma unroll
    for (int nt = 0; nt < 4; nt++)
        #pragma unroll
        for (int p = 0; p < 4; p++) fac[nt][p] = 0.0f;
    const uint32_t fBase = sb + OFF_WF + (uint32_t)(16 * w + rl) * 256;
    #pragma unroll 4
    for (int kb = 0; kb < 8; kb++) {
        uint32_t A0, A1, A2, A3;
        ldsm4(A0, A1, A2, A3, fBase + ((uint32_t)((2 * kb + ch) ^ rmod) << 4));
        uint32_t A[4] = {A0, A1, A2, A3};
        uint32_t BH[4][2], BL[4][2];
        #pragma unroll
        for (int p = 0; p < 2; p++) {
            uint32_t r0, r1, r2, r3;
            ldsm4t(r0, r1, r2, r3, hhiB + (uint32_t)kb * 1280 + (uint32_t)p * 32);
            BH[2 * p][0] = r0; BH[2 * p][1] = r1; BH[2 * p + 1][0] = r2; BH[2 * p + 1][1] = r3;
            ldsm4t(r0, r1, r2, r3, hloB + (uint32_t)kb * 1280 + (uint32_t)p * 32);
            BL[2 * p][0] = r0; BL[2 * p][1] = r1; BL[2 * p + 1][0] = r2; BL[2 * p + 1][1] = r3;
        }
        #pragma unroll
        for (int nt = 0; nt < 4; nt++) {
            mma_(fac[nt], A, BH[nt]);
            mma_(fac[nt], A, BL[nt]);
        }
    }
    float bv0 = bfh[16 * w + lid4], bv1 = bfh[16 * w + lid4 + 8];
    float fcs0 = 0.0f, fcs1 = 0.0f, hs0 = 0.0f, hs1 = 0.0f;
    #pragma unroll
    for (int nt = 0; nt < 4; nt++) {
        fcs0 += sigf(fac[nt][0] + bv0) * cst[nt * 4 + 0];
        fcs0 += sigf(fac[nt][1] + bv0) * cst[nt * 4 + 1];
        fcs1 += sigf(fac[nt][2] + bv1) * cst[nt * 4 + 2];
        fcs1 += sigf(fac[nt][3] + bv1) * cst[nt * 4 + 3];
        hs0  += harr[nt * 4 + 0] + harr[nt * 4 + 1];
        hs1  += harr[nt * 4 + 2] + harr[nt * 4 + 3];
    }
    #pragma unroll
    for (int m = 1; m <= 2; m <<= 1) {
        fcs0 += __shfl_xor_sync(0xFFFFFFFFu, fcs0, m);
        fcs1 += __shfl_xor_sync(0xFFFFFFFFu, fcs1, m);
        hs0  += __shfl_xor_sync(0xFFFFFFFFu, hs0,  m);
        hs1  += __shfl_xor_sync(0xFFFFFFFFu, hs1,  m);
    }
    if (lm4 == 0) {
        int k0 = 16 * w + lid4;
        d_fcp[blockIdx.x * MEM + k0]     = fcs0;
        d_fcp[blockIdx.x * MEM + k0 + 8] = fcs1;
        d_hsp[blockIdx.x * MEM + k0]     = hs0;
        d_hsp[blockIdx.x * MEM + k0 + 8] = hs1;
    }
}

/* -------- 5) final tree-LSTM root math -------- */
__global__ void k_final(const float* __restrict__ Wiou, const float* __restrict__ biou,
                        const float* __restrict__ Wlout, const float* __restrict__ blout,
                        float* __restrict__ out) {
    __shared__ float sh_hs[128];
    __shared__ float sh_h[128];
    int k = threadIdx.x;
    float fc = 0.0f, hs = 0.0f;
    for (int b = 0; b < NBLK; b++) {
        fc += d_fcp[b * MEM + k];
        hs += d_hsp[b * MEM + k];
    }
    sh_hs[k] = hs;
    __syncthreads();
    float iv = biou[k], ov = biou[128 + k], uv = biou[256 + k];
    #pragma unroll 8
    for (int j = 0; j < 128; j++) {
        float h = sh_hs[j];
        iv += Wiou[k * 128 + j] * h;
        ov += Wiou[(128 + k) * 128 + j] * h;
        uv += Wiou[(256 + k) * 128 + j] * h;
    }
    float cv = sigf(iv) * tanh_(uv) + fc;
    float hv = sigf(ov) * tanh_(cv);
    out[k]  = cv;
    sh_h[k] = hv;
    __syncthreads();
    float acc = blout[k];
    #pragma unroll 8
    for (int j = 0; j < 128; j++) acc += Wlout[k * 128 + j] * sh_h[j];
    out[128 + k] = acc;
}

extern "C" void kernel_launch(void* const* d_in, const int* in_sizes, int n_in,
                              void* d_out, int out_size) {
    const float* numbers = (const float*)d_in[0];
    const float* wnum    = (const float*)d_in[1];
    const float* bnum    = (const float*)d_in[2];
    const float* Wih     = (const float*)d_in[3];
    const float* Whh     = (const float*)d_in[4];
    const float* bih     = (const float*)d_in[5];
    const float* bhh     = (const float*)d_in[6];
    const float* Wfh     = (const float*)d_in[7];
    const float* bfh     = (const float*)d_in[8];
    const float* Wiou    = (const float*)d_in[9];
    const float* biou    = (const float*)d_in[10];
    const float* Wlout   = (const float*)d_in[11];
    const float* blout   = (const float*)d_in[12];
    float* out = (float*)d_out;

    cudaFuncSetAttribute(k_lstm, cudaFuncAttributeMaxDynamicSharedMemorySize, SMEM_TOTAL);

    k_stats<<<1, 32>>>(numbers);
    k_norm<<<(KN * LN + 255) / 256, 256>>>(numbers);
    k_prep<<<(G4 * MEM + MEM * MEM + G4 + 255) / 256, 256>>>(Wih, Whh, bih, bhh, Wfh, wnum, bnum);
    k_lstm<<<NBLK, THR, SMEM_TOTAL>>>(bfh);
    k_final<<<1, 128>>>(Wiou, biou, Wlout, blout, out);
}

// round 9
// speedup vs baseline: 4.9331x; 1.0987x over previous
#include <cuda_runtime.h>
#include <cstdint>

#define KN   4096
#define LN   128
#define MEM  128
#define G4   512
#define NBLK 128
#define THR  512           /* 16 warps: 2 independent groups of 8 */

/* dynamic smem layout (bytes) */
#define OFF_W    0          /* 128 KB : W_hh f16 [512 rows][128 k], 256B/row, chunk-swizzled */
#define OFF_WF   131072     /* 32 KB  : W_fh f16 [128][128], same layout */
#define OFF_HHI  163840     /* 10240 B: h_hi f16 [128 j][32 a], 80B row stride */
#define OFF_HLO  174080     /* 10240 B: h_lo */
#define SMEM_TOTAL 184320

/* ---------------- device scratch ---------------- */
__device__ float d_Xt[LN * KN];
__device__ unsigned short d_W16[G4 * MEM];    /* f16(W_hh) row-major [g][j] */
__device__ unsigned short d_Wf16[MEM * MEM];  /* f16(W_fh) */
__device__ float d_u[G4], d_v[G4];
__device__ float d_tabm[100], d_tabi[100], d_gm, d_gi;
__device__ float d_fcp[NBLK * 2 * MEM], d_hsp[NBLK * 2 * MEM];

/* ---------------- helpers ---------------- */
__device__ __forceinline__ uint32_t smem_u32(const void* p) {
    uint32_t a;
    asm("{ .reg .u64 t; cvta.to.shared.u64 t, %1; cvt.u32.u64 %0, t; }" : "=r"(a) : "l"(p));
    return a;
}
__device__ __forceinline__ float frcp(float x) { float r; asm("rcp.approx.f32 %0, %1;" : "=f"(r) : "f"(x)); return r; }
__device__ __forceinline__ float sigf(float x) { return frcp(1.0f + __expf(-x)); }
__device__ __forceinline__ float tanh_(float x) {
    float ax = fabsf(x);
    float e  = __expf(-2.0f * ax);
    float r  = (1.0f - e) * frcp(1.0f + e);
    return copysignf(r, x);
}
__device__ __forceinline__ unsigned short f16b(float f) {
    unsigned short u; asm("cvt.rn.f16.f32 %0, %1;" : "=h"(u) : "f"(f)); return u;
}
__device__ __forceinline__ float f16rt(float x) {
    unsigned short b; asm("cvt.rn.f16.f32 %0, %1;" : "=h"(b) : "f"(x));
    float r; asm("cvt.f32.f16 %0, %1;" : "=f"(r) : "h"(b));
    return r;
}
__device__ __forceinline__ unsigned f16x2pk(float lo, float hi) {
    unsigned r; asm("cvt.rn.f16x2.f32 %0, %1, %2;" : "=r"(r) : "f"(hi), "f"(lo)); return r;
}
__device__ __forceinline__ void ldsm4(uint32_t& r0, uint32_t& r1, uint32_t& r2, uint32_t& r3, uint32_t a) {
    asm volatile("ldmatrix.sync.aligned.m8n8.x4.shared.b16 {%0,%1,%2,%3}, [%4];"
                 : "=r"(r0), "=r"(r1), "=r"(r2), "=r"(r3) : "r"(a));
}
__device__ __forceinline__ void ldsm4t(uint32_t& r0, uint32_t& r1, uint32_t& r2, uint32_t& r3, uint32_t a) {
    asm volatile("ldmatrix.sync.aligned.m8n8.x4.trans.shared.b16 {%0,%1,%2,%3}, [%4];"
                 : "=r"(r0), "=r"(r1), "=r"(r2), "=r"(r3) : "r"(a));
}
__device__ __forceinline__ void mma_(float* d, const uint32_t* a, const uint32_t* b) {
    asm volatile("mma.sync.aligned.m16n8k16.row.col.f32.f16.f16.f32 "
                 "{%0,%1,%2,%3},{%4,%5,%6,%7},{%8,%9},{%0,%1,%2,%3};"
                 : "+f"(d[0]), "+f"(d[1]), "+f"(d[2]), "+f"(d[3])
                 : "r"(a[0]), "r"(a[1]), "r"(a[2]), "r"(a[3]), "r"(b[0]), "r"(b[1]));
}
__device__ __forceinline__ void barg(int id) {   /* named barrier: one 256-thread group */
    asm volatile("bar.sync %0, %1;" :: "r"(id), "r"(256) : "memory");
}

/* -------- 1) running stats over first 100 flat numbers -------- */
__global__ void k_stats(const float* __restrict__ nums) {
    if (threadIdx.x == 0 && blockIdx.x == 0) {
        float cs = 0.0f, css = 0.0f;
        for (int i = 0; i < 100; i++) {
            float x = nums[i];
            cs += x; css += x * x;
            float cap = (float)(i + 1);
            float mean = cs / cap;
            float var = fmaxf(css / cap - mean * mean, 0.0f);
            float sd = sqrtf(var);
            bool use = (cap > 3.0f) && (sd > 1e-8f);
            float inv = use ? (1.0f / sd) : 1.0f;
            d_tabm[i] = mean; d_tabi[i] = inv;
            if (i == 99) { d_gm = mean; d_gi = inv; }
        }
    }
}

/* -------- 2) normalize + transpose -------- */
__global__ void k_norm(const float* __restrict__ nums) {
    int idx = blockIdx.x * blockDim.x + threadIdx.x;
    if (idx >= KN * LN) return;
    float x = nums[idx];
    float m, inv;
    if (idx < 100) { m = d_tabm[idx]; inv = d_tabi[idx]; }
    else           { m = d_gm;        inv = d_gi;        }
    int arr = idx >> 7, t = idx & 127;
    d_Xt[t * KN + arr] = (x - m) * inv;
}

/* -------- 3) weight prep: f16 weights + rank-1 input folding -------- */
__global__ void k_prep(const float* __restrict__ Wih, const float* __restrict__ Whh,
                       const float* __restrict__ bih, const float* __restrict__ bhh,
                       const float* __restrict__ Wfh, const float* __restrict__ wnum,
                       const float* __restrict__ bnum) {
    int idx = blockIdx.x * blockDim.x + threadIdx.x;
    if (idx < G4 * MEM) d_W16[idx] = f16b(Whh[idx]);
    int i2 = idx - G4 * MEM;
    if (i2 >= 0 && i2 < MEM * MEM) d_Wf16[i2] = f16b(Wfh[i2]);
    int i3 = idx - G4 * MEM - MEM * MEM;
    if (i3 >= 0 && i3 < G4) {
        const float* row = Wih + i3 * 256 + 128;
        float u = 0.0f, v = 0.0f;
        #pragma unroll 8
        for (int j = 0; j < 128; j++) { u += row[j] * wnum[j]; v += row[j] * bnum[j]; }
        d_u[i3] = u;
        d_v[i3] = v + bih[i3] + bhh[i3];
    }
}

/* -------- 4) main LSTM: 2 independent 16-array groups x 8 warps -------- */
/* group g = wid>>3 (SMSP-balanced); warp-in-group wg owns hidden rows 16wg..16wg+16
   of all 4 gate banks for the group's 16 arrays -> epilogue fully in-register. */
__global__ void __launch_bounds__(THR, 1) k_lstm(const float* __restrict__ bfh) {
    extern __shared__ char smem[];
    const uint32_t sb = smem_u32(smem);
    const int tid = threadIdx.x;
    const int lid = tid & 31;
    const int w   = tid >> 5;
    const int g   = w >> 3;           /* group 0 / 1 */
    const int wg  = w & 7;            /* warp in group */
    const int lid4 = lid >> 2, lm4 = lid & 3;
    const int rl  = (lid & 7) | (((lid >> 3) & 1) << 3);
    const int ch  = lid >> 4;
    const int rmod = rl & 7;

    /* W_hh f16 -> smem, 256B rows, 16B-chunk XOR swizzle */
    for (int p = tid; p < G4 * 64; p += THR) {
        int row = p >> 6, q = p & 63;
        unsigned val = ((const unsigned*)d_W16)[p];
        int cc = q >> 2, wd = q & 3;
        *(unsigned*)(smem + OFF_W + row * 256 + ((cc ^ (row & 7)) << 4) + wd * 4) = val;
    }
    for (int p = tid; p < MEM * 64; p += THR) {
        int row = p >> 6, q = p & 63;
        unsigned val = ((const unsigned*)d_Wf16)[p];
        int cc = q >> 2, wd = q & 3;
        *(unsigned*)(smem + OFF_WF + row * 256 + ((cc ^ (row & 7)) << 4) + wd * 4) = val;
    }
    for (int p = tid; p < 5120; p += THR)
        *(unsigned*)(smem + OFF_HHI + p * 4) = 0u;
    __syncthreads();

    /* persistent per-thread constants */
    float u8[8], v8[8];
    #pragma unroll
    for (int b = 0; b < 4; b++)
        #pragma unroll
        for (int r = 0; r < 2; r++) {
            int k = 16 * wg + lid4 + 8 * r;
            u8[b * 2 + r] = d_u[b * 128 + k];
            v8[b * 2 + r] = d_v[b * 128 + k];
        }
    float cst[8], harr[8];
    #pragma unroll
    for (int i = 0; i < 8; i++) { cst[i] = 0.0f; harr[i] = 0.0f; }

    const uint32_t aBase = sb + OFF_W + (uint32_t)(16 * wg + rl) * 256;
    const uint32_t hhiB  = sb + OFF_HHI + (uint32_t)rl * 80 + (uint32_t)ch * 16 + (uint32_t)g * 32;
    const uint32_t hloB  = sb + OFF_HLO + (uint32_t)rl * 80 + (uint32_t)ch * 16 + (uint32_t)g * 32;
    const int gab = blockIdx.x * 32 + g * 16;
    const int bid = g + 1;            /* named barrier id for this group */

    for (int step = 0; step < LN; step++) {
        float acc[8][4];              /* [bank*2 + nt][pos] */
        #pragma unroll
        for (int i = 0; i < 8; i++)
            #pragma unroll
            for (int p = 0; p < 4; p++) acc[i][p] = 0.0f;

        #pragma unroll 4
        for (int kb = 0; kb < 8; kb++) {
            uint32_t co = (uint32_t)((2 * kb + ch) ^ rmod) << 4;
            uint32_t A[4][4];
            #pragma unroll
            for (int b = 0; b < 4; b++)
                ldsm4(A[b][0], A[b][1], A[b][2], A[b][3], aBase + (uint32_t)b * 32768 + co);
            uint32_t BH[2][2], BL[2][2];
            {
                uint32_t r0, r1, r2, r3;
                ldsm4t(r0, r1, r2, r3, hhiB + (uint32_t)kb * 1280);
                BH[0][0] = r0; BH[0][1] = r1; BH[1][0] = r2; BH[1][1] = r3;
                ldsm4t(r0, r1, r2, r3, hloB + (uint32_t)kb * 1280);
                BL[0][0] = r0; BL[0][1] = r1; BL[1][0] = r2; BL[1][1] = r3;
            }
            #pragma unroll
            for (int b = 0; b < 4; b++)
                #pragma unroll
                for (int nt = 0; nt < 2; nt++) {
                    mma_(acc[b * 2 + nt], A[b], BH[nt]);
                    mma_(acc[b * 2 + nt], A[b], BL[nt]);
                }
        }
        barg(bid);   /* group done reading old h */

        const float2* xp = (const float2*)&d_Xt[step * KN + gab];
        #pragma unroll
        for (int nt = 0; nt < 2; nt++) {
            float2 xv = __ldg(&xp[4 * nt + lm4]);
            #pragma unroll
            for (int r = 0; r < 2; r++) {
                float hhi[2], hlo[2];
                #pragma unroll
                for (int q = 0; q < 2; q++) {
                    int pos = 2 * r + q;
                    float x = q ? xv.y : xv.x;
                    float gi = acc[0 * 2 + nt][pos] + fmaf(u8[0 + r], x, v8[0 + r]);
                    float gf = acc[1 * 2 + nt][pos] + fmaf(u8[2 + r], x, v8[2 + r]);
                    float gg = acc[2 * 2 + nt][pos] + fmaf(u8[4 + r], x, v8[4 + r]);
                    float go = acc[3 * 2 + nt][pos] + fmaf(u8[6 + r], x, v8[6 + r]);
                    int cell = nt * 4 + pos;
                    float c2 = sigf(gf) * cst[cell] + sigf(gi) * tanh_(gg);
                    float h  = sigf(go) * tanh_(c2);
                    cst[cell] = c2; harr[cell] = h;
                    float hv = f16rt(h);
                    hhi[q] = hv; hlo[q] = h - hv;
                }
                int k = 16 * wg + lid4 + 8 * r;
                uint32_t off = (uint32_t)k * 80 + (uint32_t)(16 * g + 8 * nt + 2 * lm4) * 2;
                *(unsigned*)(smem + OFF_HHI + off) = f16x2pk(hhi[0], hhi[1]);
                *(unsigned*)(smem + OFF_HLO + off) = f16x2pk(hlo[0], hlo[1]);
            }
        }
        barg(bid);   /* new h visible to group */
    }

    /* -------- fused f-gate GEMM (W_fh @ h) + group reductions -------- */
    float fac[2][4];
    #pragma unroll
    for (int nt = 0; nt < 2; nt++)
        #pragma unroll
        for (int p = 0; p < 4; p++) fac[nt][p] = 0.0f;
    const uint32_t fBase = sb + OFF_WF + (uint32_t)(16 * wg + rl) * 256;
    #pragma unroll 4
    for (int kb = 0; kb < 8; kb++) {
        uint32_t A0, A1, A2, A3;
        ldsm4(A0, A1, A2, A3, fBase + ((uint32_t)((2 * kb + ch) ^ rmod) << 4));
        uint32_t A[4] = {A0, A1, A2, A3};
        uint32_t BH[2][2], BL[2][2];
        {
            uint32_t r0, r1, r2, r3;
            ldsm4t(r0, r1, r2, r3, hhiB + (uint32_t)kb * 1280);
            BH[0][0] = r0; BH[0][1] = r1; BH[1][0] = r2; BH[1][1] = r3;
            ldsm4t(r0, r1, r2, r3, hloB + (uint32_t)kb * 1280);
            BL[0][0] = r0; BL[0][1] = r1; BL[1][0] = r2; BL[1][1] = r3;
        }
        #pragma unroll
        for (int nt = 0; nt < 2; nt++) {
            mma_(fac[nt], A, BH[nt]);
            mma_(fac[nt], A, BL[nt]);
        }
    }
    float bv0 = bfh[16 * wg + lid4], bv1 = bfh[16 * wg + lid4 + 8];
    float fcs0 = 0.0f, fcs1 = 0.0f, hs0 = 0.0f, hs1 = 0.0f;
    #pragma unroll
    for (int nt = 0; nt < 2; nt++) {
        fcs0 += sigf(fac[nt][0] + bv0) * cst[nt * 4 + 0];
        fcs0 += sigf(fac[nt][1] + bv0) * cst[nt * 4 + 1];
        fcs1 += sigf(fac[nt][2] + bv1) * cst[nt * 4 + 2];
        fcs1 += sigf(fac[nt][3] + bv1) * cst[nt * 4 + 3];
        hs0  += harr[nt * 4 + 0] + harr[nt * 4 + 1];
        hs1  += harr[nt * 4 + 2] + harr[nt * 4 + 3];
    }
    #pragma unroll
    for (int m = 1; m <= 2; m <<= 1) {
        fcs0 += __shfl_xor_sync(0xFFFFFFFFu, fcs0, m);
        fcs1 += __shfl_xor_sync(0xFFFFFFFFu, fcs1, m);
        hs0  += __shfl_xor_sync(0xFFFFFFFFu, hs0,  m);
        hs1  += __shfl_xor_sync(0xFFFFFFFFu, hs1,  m);
    }
    if (lm4 == 0) {
        int k0 = 16 * wg + lid4;
        int row = blockIdx.x * 2 + g;
        d_fcp[row * MEM + k0]     = fcs0;
        d_fcp[row * MEM + k0 + 8] = fcs1;
        d_hsp[row * MEM + k0]     = hs0;
        d_hsp[row * MEM + k0 + 8] = hs1;
    }
}

/* -------- 5) final tree-LSTM root math -------- */
__global__ void k_final(const float* __restrict__ Wiou, const float* __restrict__ biou,
                        const float* __restrict__ Wlout, const float* __restrict__ blout,
                        float* __restrict__ out) {
    __shared__ float sh_hs[128];
    __shared__ float sh_h[128];
    int k = threadIdx.x;
    float fc = 0.0f, hs = 0.0f;
    for (int b = 0; b < NBLK * 2; b++) {
        fc += d_fcp[b * MEM + k];
        hs += d_hsp[b * MEM + k];
    }
    sh_hs[k] = hs;
    __syncthreads();
    float iv = biou[k], ov = biou[128 + k], uv = biou[256 + k];
    #pragma unroll 8
    for (int j = 0; j < 128; j++) {
        float h = sh_hs[j];
        iv += Wiou[k * 128 + j] * h;
        ov += Wiou[(128 + k) * 128 + j] * h;
        uv += Wiou[(256 + k) * 128 + j] * h;
    }
    float cv = sigf(iv) * tanh_(uv) + fc;
    float hv = sigf(ov) * tanh_(cv);
    out[k]  = cv;
    sh_h[k] = hv;
    __syncthreads();
    float acc = blout[k];
    #pragma unroll 8
    for (int j = 0; j < 128; j++) acc += Wlout[k * 128 + j] * sh_h[j];
    out[128 + k] = acc;
}

extern "C" void kernel_launch(void* const* d_in, const int* in_sizes, int n_in,
                              void* d_out, int out_size) {
    const float* numbers = (const float*)d_in[0];
    const float* wnum    = (const float*)d_in[1];
    const float* bnum    = (const float*)d_in[2];
    const float* Wih     = (const float*)d_in[3];
    const float* Whh     = (const float*)d_in[4];
    const float* bih     = (const float*)d_in[5];
    const float* bhh     = (const float*)d_in[6];
    const float* Wfh     = (const float*)d_in[7];
    const float* bfh     = (const float*)d_in[8];
    const float* Wiou    = (const float*)d_in[9];
    const float* biou    = (const float*)d_in[10];
    const float* Wlout   = (const float*)d_in[11];
    const float* blout   = (const float*)d_in[12];
    float* out = (float*)d_out;

    cudaFuncSetAttribute(k_lstm, cudaFuncAttributeMaxDynamicSharedMemorySize, SMEM_TOTAL);

    k_stats<<<1, 32>>>(numbers);
    k_norm<<<(KN * LN + 255) / 256, 256>>>(numbers);
    k_prep<<<(G4 * MEM + MEM * MEM + G4 + 255) / 256, 256>>>(Wih, Whh, bih, bhh, Wfh, wnum, bnum);
    k_lstm<<<NBLK, THR, SMEM_TOTAL>>>(bfh);
    k_final<<<1, 128>>>(Wiou, biou, Wlout, blout, out);
}

// round 10
// speedup vs baseline: 7.0020x; 1.4194x over previous
#include <cuda_runtime.h>
#include <cstdint>

#define KN   4096
#define LN   128
#define MEM  128
#define G4   512
#define NBLK 128
#define THR  512           /* 16 warps: 2 independent groups of 8 */

/* dynamic smem layout (bytes) */
#define OFF_W    0          /* 128 KB : W_hh f16 [512 rows][128 k], 256B/row, chunk-swizzled */
#define OFF_WF   131072     /* 32 KB  : W_fh f16 [128][128], same layout */
#define OFF_H0   163840     /* 10240 B: h f16 [128 j][32 a], 80B row stride, buffer 0 */
#define OFF_H1   174080     /* 10240 B: buffer 1 */
#define SMEM_TOTAL 184320

/* ---------------- device scratch ---------------- */
__device__ float d_Xt[LN * KN];
__device__ unsigned short d_W16[G4 * MEM];    /* f16(W_hh) row-major [g][j] */
__device__ unsigned short d_Wf16[MEM * MEM];  /* f16(W_fh) */
__device__ float d_u[G4], d_v[G4];
__device__ float d_tabm[100], d_tabi[100], d_gm, d_gi;
__device__ float d_fcp[NBLK * 2 * MEM], d_hsp[NBLK * 2 * MEM];

/* ---------------- helpers ---------------- */
__device__ __forceinline__ uint32_t smem_u32(const void* p) {
    uint32_t a;
    asm("{ .reg .u64 t; cvta.to.shared.u64 t, %1; cvt.u32.u64 %0, t; }" : "=r"(a) : "l"(p));
    return a;
}
__device__ __forceinline__ float frcp(float x) { float r; asm("rcp.approx.f32 %0, %1;" : "=f"(r) : "f"(x)); return r; }
__device__ __forceinline__ float sigf(float x) { return frcp(1.0f + __expf(-x)); }
__device__ __forceinline__ float tanh_(float x) {
    float ax = fabsf(x);
    float e  = __expf(-2.0f * ax);
    float r  = (1.0f - e) * frcp(1.0f + e);
    return copysignf(r, x);
}
/* fast HW activations for the inner loop */
__device__ __forceinline__ float tanha(float x) {
    float r; asm("tanh.approx.f32 %0, %1;" : "=f"(r) : "f"(x)); return r;
}
__device__ __forceinline__ float siga(float x) {
    return fmaf(tanha(0.5f * x), 0.5f, 0.5f);
}
__device__ __forceinline__ unsigned short f16b(float f) {
    unsigned short u; asm("cvt.rn.f16.f32 %0, %1;" : "=h"(u) : "f"(f)); return u;
}
__device__ __forceinline__ unsigned f16x2pk(float lo, float hi) {
    unsigned r; asm("cvt.rn.f16x2.f32 %0, %1, %2;" : "=r"(r) : "f"(hi), "f"(lo)); return r;
}
__device__ __forceinline__ void ldsm4(uint32_t& r0, uint32_t& r1, uint32_t& r2, uint32_t& r3, uint32_t a) {
    asm volatile("ldmatrix.sync.aligned.m8n8.x4.shared.b16 {%0,%1,%2,%3}, [%4];"
                 : "=r"(r0), "=r"(r1), "=r"(r2), "=r"(r3) : "r"(a));
}
__device__ __forceinline__ void ldsm4t(uint32_t& r0, uint32_t& r1, uint32_t& r2, uint32_t& r3, uint32_t a) {
    asm volatile("ldmatrix.sync.aligned.m8n8.x4.trans.shared.b16 {%0,%1,%2,%3}, [%4];"
                 : "=r"(r0), "=r"(r1), "=r"(r2), "=r"(r3) : "r"(a));
}
__device__ __forceinline__ void mma_(float* d, const uint32_t* a, const uint32_t* b) {
    asm volatile("mma.sync.aligned.m16n8k16.row.col.f32.f16.f16.f32 "
                 "{%0,%1,%2,%3},{%4,%5,%6,%7},{%8,%9},{%0,%1,%2,%3};"
                 : "+f"(d[0]), "+f"(d[1]), "+f"(d[2]), "+f"(d[3])
                 : "r"(a[0]), "r"(a[1]), "r"(a[2]), "r"(a[3]), "r"(b[0]), "r"(b[1]));
}
__device__ __forceinline__ void barg(int id) {   /* named barrier: one 256-thread group */
    asm volatile("bar.sync %0, %1;" :: "r"(id), "r"(256) : "memory");
}

/* -------- 1) running stats over first 100 flat numbers -------- */
__global__ void k_stats(const float* __restrict__ nums) {
    if (threadIdx.x == 0 && blockIdx.x == 0) {
        float cs = 0.0f, css = 0.0f;
        for (int i = 0; i < 100; i++) {
            float x = nums[i];
            cs += x; css += x * x;
            float cap = (float)(i + 1);
            float mean = cs / cap;
            float var = fmaxf(css / cap - mean * mean, 0.0f);
            float sd = sqrtf(var);
            bool use = (cap > 3.0f) && (sd > 1e-8f);
            float inv = use ? (1.0f / sd) : 1.0f;
            d_tabm[i] = mean; d_tabi[i] = inv;
            if (i == 99) { d_gm = mean; d_gi = inv; }
        }
    }
}

/* -------- 2) normalize + transpose -------- */
__global__ void k_norm(const float* __restrict__ nums) {
    int idx = blockIdx.x * blockDim.x + threadIdx.x;
    if (idx >= KN * LN) return;
    float x = nums[idx];
    float m, inv;
    if (idx < 100) { m = d_tabm[idx]; inv = d_tabi[idx]; }
    else           { m = d_gm;        inv = d_gi;        }
    int arr = idx >> 7, t = idx & 127;
    d_Xt[t * KN + arr] = (x - m) * inv;
}

/* -------- 3) weight prep: f16 weights + rank-1 input folding -------- */
__global__ void k_prep(const float* __restrict__ Wih, const float* __restrict__ Whh,
                       const float* __restrict__ bih, const float* __restrict__ bhh,
                       const float* __restrict__ Wfh, const float* __restrict__ wnum,
                       const float* __restrict__ bnum) {
    int idx = blockIdx.x * blockDim.x + threadIdx.x;
    if (idx < G4 * MEM) d_W16[idx] = f16b(Whh[idx]);
    int i2 = idx - G4 * MEM;
    if (i2 >= 0 && i2 < MEM * MEM) d_Wf16[i2] = f16b(Wfh[i2]);
    int i3 = idx - G4 * MEM - MEM * MEM;
    if (i3 >= 0 && i3 < G4) {
        const float* row = Wih + i3 * 256 + 128;
        float u = 0.0f, v = 0.0f;
        #pragma unroll 8
        for (int j = 0; j < 128; j++) { u += row[j] * wnum[j]; v += row[j] * bnum[j]; }
        d_u[i3] = u;
        d_v[i3] = v + bih[i3] + bhh[i3];
    }
}

/* -------- 4) main LSTM: 2 groups x 8 warps, single-term f16 h, double-buffered -------- */
__global__ void __launch_bounds__(THR, 1) k_lstm(const float* __restrict__ bfh) {
    extern __shared__ char smem[];
    const uint32_t sb = smem_u32(smem);
    const int tid = threadIdx.x;
    const int lid = tid & 31;
    const int w   = tid >> 5;
    const int g   = w >> 3;           /* group 0 / 1 */
    const int wg  = w & 7;            /* warp in group */
    const int lid4 = lid >> 2, lm4 = lid & 3;
    const int rl  = (lid & 7) | (((lid >> 3) & 1) << 3);
    const int ch  = lid >> 4;
    const int rmod = rl & 7;

    /* W_hh f16 -> smem, 256B rows, 16B-chunk XOR swizzle */
    for (int p = tid; p < G4 * 64; p += THR) {
        int row = p >> 6, q = p & 63;
        unsigned val = ((const unsigned*)d_W16)[p];
        int cc = q >> 2, wd = q & 3;
        *(unsigned*)(smem + OFF_W + row * 256 + ((cc ^ (row & 7)) << 4) + wd * 4) = val;
    }
    for (int p = tid; p < MEM * 64; p += THR) {
        int row = p >> 6, q = p & 63;
        unsigned val = ((const unsigned*)d_Wf16)[p];
        int cc = q >> 2, wd = q & 3;
        *(unsigned*)(smem + OFF_WF + row * 256 + ((cc ^ (row & 7)) << 4) + wd * 4) = val;
    }
    for (int p = tid; p < 5120; p += THR)
        *(unsigned*)(smem + OFF_H0 + p * 4) = 0u;
    __syncthreads();

    /* persistent per-thread constants */
    float u8[8], v8[8];
    #pragma unroll
    for (int b = 0; b < 4; b++)
        #pragma unroll
        for (int r = 0; r < 2; r++) {
            int k = 16 * wg + lid4 + 8 * r;
            u8[b * 2 + r] = d_u[b * 128 + k];
            v8[b * 2 + r] = d_v[b * 128 + k];
        }
    float cst[8], harr[8];
    #pragma unroll
    for (int i = 0; i < 8; i++) { cst[i] = 0.0f; harr[i] = 0.0f; }

    const uint32_t aBase = sb + OFF_W + (uint32_t)(16 * wg + rl) * 256;
    const uint32_t hB0   = sb + OFF_H0 + (uint32_t)rl * 80 + (uint32_t)ch * 16 + (uint32_t)g * 32;
    const uint32_t hB1   = sb + OFF_H1 + (uint32_t)rl * 80 + (uint32_t)ch * 16 + (uint32_t)g * 32;
    const int gab = blockIdx.x * 32 + g * 16;
    const int bid = g + 1;            /* named barrier id for this group */
    /* per-thread h write offset pieces */
    const uint32_t wcol = (uint32_t)(16 * g + 2 * lm4) * 2;

    for (int step = 0; step < LN; step++) {
        const int p = step & 1;                 /* read buffer: holds h(step-1) */
        const uint32_t hRd = p ? hB1 : hB0;
        char* hWr = smem + (p ? OFF_H0 : OFF_H1);

        float acc[8][4];              /* [bank*2 + nt][pos] */
        #pragma unroll
        for (int i = 0; i < 8; i++)
            #pragma unroll
            for (int q = 0; q < 4; q++) acc[i][q] = 0.0f;

        #pragma unroll 4
        for (int kb = 0; kb < 8; kb++) {
            uint32_t co = (uint32_t)((2 * kb + ch) ^ rmod) << 4;
            uint32_t A[4][4];
            #pragma unroll
            for (int b = 0; b < 4; b++)
                ldsm4(A[b][0], A[b][1], A[b][2], A[b][3], aBase + (uint32_t)b * 32768 + co);
            uint32_t BH[2][2];
            {
                uint32_t r0, r1, r2, r3;
                ldsm4t(r0, r1, r2, r3, hRd + (uint32_t)kb * 1280);
                BH[0][0] = r0; BH[0][1] = r1; BH[1][0] = r2; BH[1][1] = r3;
            }
            #pragma unroll
            for (int b = 0; b < 4; b++)
                #pragma unroll
                for (int nt = 0; nt < 2; nt++)
                    mma_(acc[b * 2 + nt], A[b], BH[nt]);
        }

        /* epilogue: gates -> (c,h), write h(step) into the other buffer */
        const float2* xp = (const float2*)&d_Xt[step * KN + gab];
        #pragma unroll
        for (int nt = 0; nt < 2; nt++) {
            float2 xv = __ldg(&xp[4 * nt + lm4]);
            #pragma unroll
            for (int r = 0; r < 2; r++) {
                float hv[2];
                #pragma unroll
                for (int q = 0; q < 2; q++) {
                    int pos = 2 * r + q;
                    float x = q ? xv.y : xv.x;
                    float gi = acc[0 * 2 + nt][pos] + fmaf(u8[0 + r], x, v8[0 + r]);
                    float gf = acc[1 * 2 + nt][pos] + fmaf(u8[2 + r], x, v8[2 + r]);
                    float gg = acc[2 * 2 + nt][pos] + fmaf(u8[4 + r], x, v8[4 + r]);
                    float go = acc[3 * 2 + nt][pos] + fmaf(u8[6 + r], x, v8[6 + r]);
                    int cell = nt * 4 + pos;
                    float c2 = siga(gf) * cst[cell] + siga(gi) * tanha(gg);
                    float h  = siga(go) * tanha(c2);
                    cst[cell] = c2; harr[cell] = h;
                    hv[q] = h;
                }
                int k = 16 * wg + lid4 + 8 * r;
                uint32_t off = (uint32_t)k * 80 + wcol + (uint32_t)nt * 16;
                *(unsigned*)(hWr + off) = f16x2pk(hv[0], hv[1]);
            }
        }
        barg(bid);   /* h(step) visible; all group reads of hRd complete */
    }

    /* -------- fused f-gate GEMM (W_fh @ h_final, h_final in buffer 0) -------- */
    float fac[2][4];
    #pragma unroll
    for (int nt = 0; nt < 2; nt++)
        #pragma unroll
        for (int q = 0; q < 4; q++) fac[nt][q] = 0.0f;
    const uint32_t fBase = sb + OFF_WF + (uint32_t)(16 * wg + rl) * 256;
    #pragma unroll 4
    for (int kb = 0; kb < 8; kb++) {
        uint32_t A0, A1, A2, A3;
        ldsm4(A0, A1, A2, A3, fBase + ((uint32_t)((2 * kb + ch) ^ rmod) << 4));
        uint32_t A[4] = {A0, A1, A2, A3};
        uint32_t BH[2][2];
        {
            uint32_t r0, r1, r2, r3;
            ldsm4t(r0, r1, r2, r3, hB0 + (uint32_t)kb * 1280);
            BH[0][0] = r0; BH[0][1] = r1; BH[1][0] = r2; BH[1][1] = r3;
        }
        #pragma unroll
        for (int nt = 0; nt < 2; nt++)
            mma_(fac[nt], A, BH[nt]);
    }
    /* exact activations in the one-shot epilogue */
    float bv0 = bfh[16 * wg + lid4], bv1 = bfh[16 * wg + lid4 + 8];
    float fcs0 = 0.0f, fcs1 = 0.0f, hs0 = 0.0f, hs1 = 0.0f;
    #pragma unroll
    for (int nt = 0; nt < 2; nt++) {
        fcs0 += sigf(fac[nt][0] + bv0) * cst[nt * 4 + 0];
        fcs0 += sigf(fac[nt][1] + bv0) * cst[nt * 4 + 1];
        fcs1 += sigf(fac[nt][2] + bv1) * cst[nt * 4 + 2];
        fcs1 += sigf(fac[nt][3] + bv1) * cst[nt * 4 + 3];
        hs0  += harr[nt * 4 + 0] + harr[nt * 4 + 1];
        hs1  += harr[nt * 4 + 2] + harr[nt * 4 + 3];
    }
    #pragma unroll
    for (int m = 1; m <= 2; m <<= 1) {
        fcs0 += __shfl_xor_sync(0xFFFFFFFFu, fcs0, m);
        fcs1 += __shfl_xor_sync(0xFFFFFFFFu, fcs1, m);
        hs0  += __shfl_xor_sync(0xFFFFFFFFu, hs0,  m);
        hs1  += __shfl_xor_sync(0xFFFFFFFFu, hs1,  m);
    }
    if (lm4 == 0) {
        int k0 = 16 * wg + lid4;
        int row = blockIdx.x * 2 + g;
        d_fcp[row * MEM + k0]     = fcs0;
        d_fcp[row * MEM + k0 + 8] = fcs1;
        d_hsp[row * MEM + k0]     = hs0;
        d_hsp[row * MEM + k0 + 8] = hs1;
    }
}

/* -------- 5) final tree-LSTM root math -------- */
__global__ void k_final(const float* __restrict__ Wiou, const float* __restrict__ biou,
                        const float* __restrict__ Wlout, const float* __restrict__ blout,
                        float* __restrict__ out) {
    __shared__ float sh_hs[128];
    __shared__ float sh_h[128];
    int k = threadIdx.x;
    float fc = 0.0f, hs = 0.0f;
    for (int b = 0; b < NBLK * 2; b++) {
        fc += d_fcp[b * MEM + k];
        hs += d_hsp[b * MEM + k];
    }
    sh_hs[k] = hs;
    __syncthreads();
    float iv = biou[k], ov = biou[128 + k], uv = biou[256 + k];
    #pragma unroll 8
    for (int j = 0; j < 128; j++) {
        float h = sh_hs[j];
        iv += Wiou[k * 128 + j] * h;
        ov += Wiou[(128 + k) * 128 + j] * h;
        uv += Wiou[(256 + k) * 128 + j] * h;
    }
    float cv = sigf(iv) * tanh_(uv) + fc;
    float hv = sigf(ov) * tanh_(cv);
    out[k]  = cv;
    sh_h[k] = hv;
    __syncthreads();
    float acc = blout[k];
    #pragma unroll 8
    for (int j = 0; j < 128; j++) acc += Wlout[k * 128 + j] * sh_h[j];
    out[128 + k] = acc;
}

extern "C" void kernel_launch(void* const* d_in, const int* in_sizes, int n_in,
                              void* d_out, int out_size) {
    const float* numbers = (const float*)d_in[0];
    const float* wnum    = (const float*)d_in[1];
    const float* bnum    = (const float*)d_in[2];
    const float* Wih     = (const float*)d_in[3];
    const float* Whh     = (const float*)d_in[4];
    const float* bih     = (const float*)d_in[5];
    const float* bhh     = (const float*)d_in[6];
    const float* Wfh     = (const float*)d_in[7];
    const float* bfh     = (const float*)d_in[8];
    const float* Wiou    = (const float*)d_in[9];
    const float* biou    = (const float*)d_in[10];
    const float* Wlout   = (const float*)d_in[11];
    const float* blout   = (const float*)d_in[12];
    float* out = (float*)d_out;

    cudaFuncSetAttribute(k_lstm, cudaFuncAttributeMaxDynamicSharedMemorySize, SMEM_TOTAL);

    k_stats<<<1, 32>>>(numbers);
    k_norm<<<(KN * LN + 255) / 256, 256>>>(numbers);
    k_prep<<<(G4 * MEM + MEM * MEM + G4 + 255) / 256, 256>>>(Wih, Whh, bih, bhh, Wfh, wnum, bnum);
    k_lstm<<<NBLK, THR, SMEM_TOTAL>>>(bfh);
    k_final<<<1, 128>>>(Wiou, biou, Wlout, blout, out);
}

// round 11
// speedup vs baseline: 8.5629x; 1.2229x over previous
#include <cuda_runtime.h>
#include <cstdint>

#define KN   4096
#define LN   128
#define MEM  128
#define G4   512
#define NBLK 128
#define THR  512           /* 16 warps, one merged group, 32 arrays */

/* ---------------- device scratch ---------------- */
__device__ float d_Xt[LN * KN];
__device__ unsigned short d_W16[G4 * MEM];    /* f16(W_hh) row-major [gate row g][j] */
__device__ unsigned short d_Wf16[MEM * MEM];  /* f16(W_fh) */
__device__ float d_u[G4], d_v[G4];
__device__ float d_tabm[100], d_tabi[100], d_gm, d_gi;
__device__ float d_fcp[NBLK * MEM], d_hsp[NBLK * MEM];

/* ---------------- helpers ---------------- */
__device__ __forceinline__ uint32_t smem_u32(const void* p) {
    uint32_t a;
    asm("{ .reg .u64 t; cvta.to.shared.u64 t, %1; cvt.u32.u64 %0, t; }" : "=r"(a) : "l"(p));
    return a;
}
__device__ __forceinline__ float frcp(float x) { float r; asm("rcp.approx.f32 %0, %1;" : "=f"(r) : "f"(x)); return r; }
__device__ __forceinline__ float sigf(float x) { return frcp(1.0f + __expf(-x)); }
__device__ __forceinline__ float tanh_(float x) {
    float ax = fabsf(x);
    float e  = __expf(-2.0f * ax);
    float r  = (1.0f - e) * frcp(1.0f + e);
    return copysignf(r, x);
}
__device__ __forceinline__ float tanha(float x) {
    float r; asm("tanh.approx.f32 %0, %1;" : "=f"(r) : "f"(x)); return r;
}
__device__ __forceinline__ float siga(float x) {
    return fmaf(tanha(0.5f * x), 0.5f, 0.5f);
}
__device__ __forceinline__ unsigned short f16b(float f) {
    unsigned short u; asm("cvt.rn.f16.f32 %0, %1;" : "=h"(u) : "f"(f)); return u;
}
__device__ __forceinline__ float f16tof(unsigned short u) {
    float f; asm("cvt.f32.f16 %0, %1;" : "=f"(f) : "h"(u)); return f;
}
__device__ __forceinline__ unsigned f16x2pk(float lo, float hi) {
    unsigned r; asm("cvt.rn.f16x2.f32 %0, %1, %2;" : "=r"(r) : "f"(hi), "f"(lo)); return r;
}
__device__ __forceinline__ void ldsm4t(uint32_t& r0, uint32_t& r1, uint32_t& r2, uint32_t& r3, uint32_t a) {
    asm volatile("ldmatrix.sync.aligned.m8n8.x4.trans.shared.b16 {%0,%1,%2,%3}, [%4];"
                 : "=r"(r0), "=r"(r1), "=r"(r2), "=r"(r3) : "r"(a));
}
__device__ __forceinline__ void mma_(float* d, const uint32_t* a, const uint32_t* b) {
    asm volatile("mma.sync.aligned.m16n8k16.row.col.f32.f16.f16.f32 "
                 "{%0,%1,%2,%3},{%4,%5,%6,%7},{%8,%9},{%0,%1,%2,%3};"
                 : "+f"(d[0]), "+f"(d[1]), "+f"(d[2]), "+f"(d[3])
                 : "r"(a[0]), "r"(a[1]), "r"(a[2]), "r"(a[3]), "r"(b[0]), "r"(b[1]));
}

/* -------- 1) running stats over first 100 flat numbers -------- */
__global__ void k_stats(const float* __restrict__ nums) {
    if (threadIdx.x == 0 && blockIdx.x == 0) {
        float cs = 0.0f, css = 0.0f;
        for (int i = 0; i < 100; i++) {
            float x = nums[i];
            cs += x; css += x * x;
            float cap = (float)(i + 1);
            float mean = cs / cap;
            float var = fmaxf(css / cap - mean * mean, 0.0f);
            float sd = sqrtf(var);
            bool use = (cap > 3.0f) && (sd > 1e-8f);
            float inv = use ? (1.0f / sd) : 1.0f;
            d_tabm[i] = mean; d_tabi[i] = inv;
            if (i == 99) { d_gm = mean; d_gi = inv; }
        }
    }
}

/* -------- 2) normalize + transpose -------- */
__global__ void k_norm(const float* __restrict__ nums) {
    int idx = blockIdx.x * blockDim.x + threadIdx.x;
    if (idx >= KN * LN) return;
    float x = nums[idx];
    float m, inv;
    if (idx < 100) { m = d_tabm[idx]; inv = d_tabi[idx]; }
    else           { m = d_gm;        inv = d_gi;        }
    int arr = idx >> 7, t = idx & 127;
    d_Xt[t * KN + arr] = (x - m) * inv;
}

/* -------- 3) weight prep: f16 weights + rank-1 input folding -------- */
__global__ void k_prep(const float* __restrict__ Wih, const float* __restrict__ Whh,
                       const float* __restrict__ bih, const float* __restrict__ bhh,
                       const float* __restrict__ Wfh, const float* __restrict__ wnum,
                       const float* __restrict__ bnum) {
    int idx = blockIdx.x * blockDim.x + threadIdx.x;
    if (idx < G4 * MEM) d_W16[idx] = f16b(Whh[idx]);
    int i2 = idx - G4 * MEM;
    if (i2 >= 0 && i2 < MEM * MEM) d_Wf16[i2] = f16b(Wfh[i2]);
    int i3 = idx - G4 * MEM - MEM * MEM;
    if (i3 >= 0 && i3 < G4) {
        const float* row = Wih + i3 * 256 + 128;
        float u = 0.0f, v = 0.0f;
        #pragma unroll 8
        for (int j = 0; j < 128; j++) { u += row[j] * wnum[j]; v += row[j] * bnum[j]; }
        d_u[i3] = u;
        d_v[i3] = v + bih[i3] + bhh[i3];
    }
}

/* -------- 4) main LSTM: register-resident W, 16 warps x 32 arrays -------- */
/* warp w owns hidden units 8w..8w+8, ALL 4 gate banks (rows permuted so
   m16 tile mt = banks {2mt, 2mt+1} for those units). Thread (lid4,lm4) ends up
   with the full (i,f,g,o) quadruple for unit u=8w+lid4, arrays {nt*8+2lm4, +1}. */
__global__ void __launch_bounds__(THR, 1) k_lstm(const float* __restrict__ bfh) {
    __shared__ unsigned short shh[2][128 * 40];  /* h f16 [buf][unit j][array a], 80B row stride */
    __shared__ float shc[128 * 33];              /* final c [unit][array], padded */
    __shared__ float shred[2][128];

    const int tid = threadIdx.x;
    const int lid = tid & 31;
    const int w   = tid >> 5;
    const int lid4 = lid >> 2, lm4 = lid & 3;
    const int rl  = (lid & 7) | (((lid >> 3) & 1) << 3);
    const int ch  = lid >> 4;
    const int u   = 8 * w + lid4;                /* this thread's hidden unit */

    /* ---- A fragments of W_hh, loaded ONCE from global (64 regs) ---- */
    uint32_t A[2][8][4];
    #pragma unroll
    for (int mt = 0; mt < 2; mt++)
        #pragma unroll
        for (int kb = 0; kb < 8; kb++) {
            const unsigned short* r0 = &d_W16[((2 * mt)     * 128 + u) * 128 + kb * 16 + 2 * lm4];
            const unsigned short* r1 = &d_W16[((2 * mt + 1) * 128 + u) * 128 + kb * 16 + 2 * lm4];
            A[mt][kb][0] = *(const uint32_t*)r0;
            A[mt][kb][1] = *(const uint32_t*)r1;
            A[mt][kb][2] = *(const uint32_t*)(r0 + 8);
            A[mt][kb][3] = *(const uint32_t*)(r1 + 8);
        }

    float u4[4], v4[4];
    #pragma unroll
    for (int b = 0; b < 4; b++) { u4[b] = d_u[b * 128 + u]; v4[b] = d_v[b * 128 + u]; }

    float cst[8];
    #pragma unroll
    for (int i = 0; i < 8; i++) cst[i] = 0.0f;

    /* zero read buffer 0 */
    for (int p = tid; p < 2560; p += THR) ((uint32_t*)shh[0])[p] = 0u;
    __syncthreads();

    const uint32_t sb_h = smem_u32(shh);
    const uint32_t hLane = (uint32_t)rl * 80 + (uint32_t)ch * 16;
    const int gab = blockIdx.x * 32;

    for (int step = 0; step < LN; step++) {
        const uint32_t hRd = sb_h + (uint32_t)(step & 1) * 10240 + hLane;
        unsigned short* hw = shh[(step & 1) ^ 1];

        float acc[2][4][4];
        #pragma unroll
        for (int mt = 0; mt < 2; mt++)
            #pragma unroll
            for (int nt = 0; nt < 4; nt++)
                #pragma unroll
                for (int q = 0; q < 4; q++) acc[mt][nt][q] = 0.0f;

        #pragma unroll
        for (int kb = 0; kb < 8; kb++) {
            uint32_t B[4][2];
            {
                uint32_t q0, q1, q2, q3;
                ldsm4t(q0, q1, q2, q3, hRd + (uint32_t)kb * 1280);
                B[0][0] = q0; B[0][1] = q1; B[1][0] = q2; B[1][1] = q3;
                ldsm4t(q0, q1, q2, q3, hRd + (uint32_t)kb * 1280 + 32);
                B[2][0] = q0; B[2][1] = q1; B[3][0] = q2; B[3][1] = q3;
            }
            #pragma unroll
            for (int mt = 0; mt < 2; mt++)
                #pragma unroll
                for (int nt = 0; nt < 4; nt++)
                    mma_(acc[mt][nt], A[mt][kb], B[nt]);
        }

        /* epilogue: full (i,f,g,o) per cell in-register */
        const float2* xp = (const float2*)&d_Xt[step * KN + gab];
        #pragma unroll
        for (int nt = 0; nt < 4; nt++) {
            float2 xv = __ldg(&xp[nt * 4 + lm4]);
            float hv[2];
            #pragma unroll
            for (int q = 0; q < 2; q++) {
                float x  = q ? xv.y : xv.x;
                float gi = acc[0][nt][q]     + fmaf(u4[0], x, v4[0]);
                float gf = acc[0][nt][2 + q] + fmaf(u4[1], x, v4[1]);
                float gg = acc[1][nt][q]     + fmaf(u4[2], x, v4[2]);
                float go = acc[1][nt][2 + q] + fmaf(u4[3], x, v4[3]);
                float c2 = siga(gf) * cst[nt * 2 + q] + siga(gi) * tanha(gg);
                float h  = siga(go) * tanha(c2);
                cst[nt * 2 + q] = c2;
                hv[q] = h;
            }
            *(unsigned*)&hw[u * 40 + nt * 8 + 2 * lm4] = f16x2pk(hv[0], hv[1]);
        }
        __syncthreads();
    }

    /* ---- stage c to smem for the f-gate pass ---- */
    #pragma unroll
    for (int nt = 0; nt < 4; nt++) {
        shc[u * 33 + nt * 8 + 2 * lm4]     = cst[nt * 2 + 0];
        shc[u * 33 + nt * 8 + 2 * lm4 + 1] = cst[nt * 2 + 1];
    }
    __syncthreads();

    /* ---- f-gate GEMM: warp w -> m16 tile (w&7), n-half (w>>3) ---- */
    const int mt = w & 7, nh = w >> 3;
    uint32_t Af[8][4];
    #pragma unroll
    for (int kb = 0; kb < 8; kb++) {
        const unsigned short* r0 = &d_Wf16[(16 * mt + lid4) * 128 + kb * 16 + 2 * lm4];
        const unsigned short* r1 = r0 + 8 * 128;
        Af[kb][0] = *(const uint32_t*)r0;
        Af[kb][1] = *(const uint32_t*)r1;
        Af[kb][2] = *(const uint32_t*)(r0 + 8);
        Af[kb][3] = *(const uint32_t*)(r1 + 8);
    }
    float fa[2][4];
    #pragma unroll
    for (int nt = 0; nt < 2; nt++)
        #pragma unroll
        for (int q = 0; q < 4; q++) fa[nt][q] = 0.0f;
    const uint32_t hF = sb_h + hLane + (uint32_t)nh * 32;   /* final h is in buffer 0 */
    #pragma unroll
    for (int kb = 0; kb < 8; kb++) {
        uint32_t q0, q1, q2, q3;
        ldsm4t(q0, q1, q2, q3, hF + (uint32_t)kb * 1280);
        uint32_t B0[2] = {q0, q1}, B1[2] = {q2, q3};
        mma_(fa[0], Af[kb], B0);
        mma_(fa[1], Af[kb], B1);
    }
    const int r0 = 16 * mt + lid4, r1 = r0 + 8;
    float b0 = bfh[r0], b1 = bfh[r1];
    float f0 = 0.0f, f1 = 0.0f;
    #pragma unroll
    for (int nt = 0; nt < 2; nt++)
        #pragma unroll
        for (int q = 0; q < 2; q++) {
            int col = nh * 16 + nt * 8 + 2 * lm4 + q;
            f0 += sigf(fa[nt][q]     + b0) * shc[r0 * 33 + col];
            f1 += sigf(fa[nt][2 + q] + b1) * shc[r1 * 33 + col];
        }
    f0 += __shfl_xor_sync(0xFFFFFFFFu, f0, 1);
    f0 += __shfl_xor_sync(0xFFFFFFFFu, f0, 2);
    f1 += __shfl_xor_sync(0xFFFFFFFFu, f1, 1);
    f1 += __shfl_xor_sync(0xFFFFFFFFu, f1, 2);
    if (lm4 == 0) { shred[nh][r0] = f0; shred[nh][r1] = f1; }
    __syncthreads();

    if (tid < 128) {
        float fc = shred[0][tid] + shred[1][tid];
        float hs = 0.0f;
        #pragma unroll 8
        for (int a = 0; a < 32; a++) hs += f16tof(shh[0][tid * 40 + a]);
        d_fcp[blockIdx.x * MEM + tid] = fc;
        d_hsp[blockIdx.x * MEM + tid] = hs;
    }
}

/* -------- 5) final tree-LSTM root math -------- */
__global__ void k_final(const float* __restrict__ Wiou, const float* __restrict__ biou,
                        const float* __restrict__ Wlout, const float* __restrict__ blout,
                        float* __restrict__ out) {
    __shared__ float sh_hs[128];
    __shared__ float sh_h[128];
    int k = threadIdx.x;
    float fc = 0.0f, hs = 0.0f;
    for (int b = 0; b < NBLK; b++) {
        fc += d_fcp[b * MEM + k];
        hs += d_hsp[b * MEM + k];
    }
    sh_hs[k] = hs;
    __syncthreads();
    float iv = biou[k], ov = biou[128 + k], uv = biou[256 + k];
    #pragma unroll 8
    for (int j = 0; j < 128; j++) {
        float h = sh_hs[j];
        iv += Wiou[k * 128 + j] * h;
        ov += Wiou[(128 + k) * 128 + j] * h;
        uv += Wiou[(256 + k) * 128 + j] * h;
    }
    float cv = sigf(iv) * tanh_(uv) + fc;
    float hv = sigf(ov) * tanh_(cv);
    out[k]  = cv;
    sh_h[k] = hv;
    __syncthreads();
    float acc = blout[k];
    #pragma unroll 8
    for (int j = 0; j < 128; j++) acc += Wlout[k * 128 + j] * sh_h[j];
    out[128 + k] = acc;
}

extern "C" void kernel_launch(void* const* d_in, const int* in_sizes, int n_in,
                              void* d_out, int out_size) {
    const float* numbers = (const float*)d_in[0];
    const float* wnum    = (const float*)d_in[1];
    const float* bnum    = (const float*)d_in[2];
    const float* Wih     = (const float*)d_in[3];
    const float* Whh     = (const float*)d_in[4];
    const float* bih     = (const float*)d_in[5];
    const float* bhh     = (const float*)d_in[6];
    const float* Wfh     = (const float*)d_in[7];
    const float* bfh     = (const float*)d_in[8];
    const float* Wiou    = (const float*)d_in[9];
    const float* biou    = (const float*)d_in[10];
    const float* Wlout   = (const float*)d_in[11];
    const float* blout   = (const float*)d_in[12];
    float* out = (float*)d_out;

    k_stats<<<1, 32>>>(numbers);
    k_norm<<<(KN * LN + 255) / 256, 256>>>(numbers);
    k_prep<<<(G4 * MEM + MEM * MEM + G4 + 255) / 256, 256>>>(Wih, Whh, bih, bhh, Wfh, wnum, bnum);
    k_lstm<<<NBLK, THR>>>(bfh);
    k_final<<<1, 128>>>(Wiou, biou, Wlout, blout, out);
}

// round 12
// speedup vs baseline: 8.6809x; 1.0138x over previous
#include <cuda_runtime.h>
#include <cstdint>

#define KN   4096
#define LN   128
#define MEM  128
#define G4   512
#define NBLK 128
#define THR  512           /* 16 warps, one merged group, 32 arrays */

/* ---------------- device scratch ---------------- */
__device__ float d_Xt[LN * KN];
__device__ unsigned short d_W16[G4 * MEM];    /* f16(W_hh) row-major [gate row g][j] */
__device__ unsigned short d_Wf16[MEM * MEM];  /* f16(W_fh) */
__device__ float d_u[G4], d_v[G4];
__device__ float d_tabm[100], d_tabi[100], d_gm, d_gi;
__device__ float d_fcp[NBLK * MEM], d_hsp[NBLK * MEM];

/* ---------------- helpers ---------------- */
__device__ __forceinline__ uint32_t smem_u32(const void* p) {
    uint32_t a;
    asm("{ .reg .u64 t; cvta.to.shared.u64 t, %1; cvt.u32.u64 %0, t; }" : "=r"(a) : "l"(p));
    return a;
}
__device__ __forceinline__ float frcp(float x) { float r; asm("rcp.approx.f32 %0, %1;" : "=f"(r) : "f"(x)); return r; }
__device__ __forceinline__ float sigf(float x) { return frcp(1.0f + __expf(-x)); }
__device__ __forceinline__ float tanh_(float x) {
    float ax = fabsf(x);
    float e  = __expf(-2.0f * ax);
    float r  = (1.0f - e) * frcp(1.0f + e);
    return copysignf(r, x);
}
__device__ __forceinline__ float tanha(float x) {
    float r; asm("tanh.approx.f32 %0, %1;" : "=f"(r) : "f"(x)); return r;
}
__device__ __forceinline__ float siga(float x) {
    return fmaf(tanha(0.5f * x), 0.5f, 0.5f);
}
__device__ __forceinline__ unsigned short f16b(float f) {
    unsigned short u; asm("cvt.rn.f16.f32 %0, %1;" : "=h"(u) : "f"(f)); return u;
}
__device__ __forceinline__ float f16tof(unsigned short u) {
    float f; asm("cvt.f32.f16 %0, %1;" : "=f"(f) : "h"(u)); return f;
}
__device__ __forceinline__ unsigned f16x2pk(float lo, float hi) {
    unsigned r; asm("cvt.rn.f16x2.f32 %0, %1, %2;" : "=r"(r) : "f"(hi), "f"(lo)); return r;
}
__device__ __forceinline__ void ldsm4t(uint32_t& r0, uint32_t& r1, uint32_t& r2, uint32_t& r3, uint32_t a) {
    asm volatile("ldmatrix.sync.aligned.m8n8.x4.trans.shared.b16 {%0,%1,%2,%3}, [%4];"
                 : "=r"(r0), "=r"(r1), "=r"(r2), "=r"(r3) : "r"(a));
}
__device__ __forceinline__ void mma_(float* d, const uint32_t* a, const uint32_t* b) {
    asm volatile("mma.sync.aligned.m16n8k16.row.col.f32.f16.f16.f32 "
                 "{%0,%1,%2,%3},{%4,%5,%6,%7},{%8,%9},{%0,%1,%2,%3};"
                 : "+f"(d[0]), "+f"(d[1]), "+f"(d[2]), "+f"(d[3])
                 : "r"(a[0]), "r"(a[1]), "r"(a[2]), "r"(a[3]), "r"(b[0]), "r"(b[1]));
}

/* -------- 1) running stats over first 100 flat numbers (smem-staged) -------- */
__global__ void k_stats(const float* __restrict__ nums) {
    __shared__ float s[100];
    __shared__ float scs[100], scss[100];
    int t = threadIdx.x;
    if (t < 100) s[t] = nums[t];
    __syncthreads();
    if (t == 0) {
        float cs = 0.0f, css = 0.0f;
        #pragma unroll 4
        for (int i = 0; i < 100; i++) {
            float x = s[i];
            cs += x; css += x * x;
            scs[i] = cs; scss[i] = css;
        }
    }
    __syncthreads();
    if (t < 100) {
        float cap  = (float)(t + 1);
        float mean = scs[t] / cap;
        float var  = fmaxf(scss[t] / cap - mean * mean, 0.0f);
        float sd   = sqrtf(var);
        bool  use  = (cap > 3.0f) && (sd > 1e-8f);
        float inv  = use ? (1.0f / sd) : 1.0f;
        d_tabm[t] = mean; d_tabi[t] = inv;
        if (t == 99) { d_gm = mean; d_gi = inv; }
    }
}

/* -------- 2) normalize + transpose -------- */
__global__ void k_norm(const float* __restrict__ nums) {
    int idx = blockIdx.x * blockDim.x + threadIdx.x;
    if (idx >= KN * LN) return;
    float x = nums[idx];
    float m, inv;
    if (idx < 100) { m = d_tabm[idx]; inv = d_tabi[idx]; }
    else           { m = d_gm;        inv = d_gi;        }
    int arr = idx >> 7, t = idx & 127;
    d_Xt[t * KN + arr] = (x - m) * inv;
}

/* -------- 3) weight prep: f16 weights + rank-1 input folding -------- */
__global__ void k_prep(const float* __restrict__ Wih, const float* __restrict__ Whh,
                       const float* __restrict__ bih, const float* __restrict__ bhh,
                       const float* __restrict__ Wfh, const float* __restrict__ wnum,
                       const float* __restrict__ bnum) {
    int idx = blockIdx.x * blockDim.x + threadIdx.x;
    if (idx < G4 * MEM) d_W16[idx] = f16b(Whh[idx]);
    int i2 = idx - G4 * MEM;
    if (i2 >= 0 && i2 < MEM * MEM) d_Wf16[i2] = f16b(Wfh[i2]);
    int i3 = idx - G4 * MEM - MEM * MEM;
    if (i3 >= 0 && i3 < G4) {
        const float* row = Wih + i3 * 256 + 128;
        float u = 0.0f, v = 0.0f;
        #pragma unroll 8
        for (int j = 0; j < 128; j++) { u += row[j] * wnum[j]; v += row[j] * bnum[j]; }
        d_u[i3] = u;
        d_v[i3] = v + bih[i3] + bhh[i3];
    }
}

/* -------- 4) main LSTM: register-resident W, phase-split MMA for overlap -------- */
/* warp w owns hidden units 8w..8w+8, all 4 gate banks. Thread (lid4,lm4) holds the
   full (i,f,g,o) quadruple for unit u=8w+lid4, arrays {nt*8+2lm4, +1}.
   Per step: prefetch x; MMA phase A (arrays 0-15); MMA phase B (16-31); epilogue —
   phase-A cells' MUFU overlaps phase-B tensor work via scoreboarding. */
__global__ void __launch_bounds__(THR, 1) k_lstm(const float* __restrict__ bfh) {
    __shared__ unsigned short shh[2][128 * 40];  /* h f16 [buf][unit j][array a], 80B row stride */
    __shared__ float shc[128 * 33];              /* final c [unit][array], padded */
    __shared__ float shred[2][128];

    const int tid = threadIdx.x;
    const int lid = tid & 31;
    const int w   = tid >> 5;
    const int lid4 = lid >> 2, lm4 = lid & 3;
    const int rl  = (lid & 7) | (((lid >> 3) & 1) << 3);
    const int ch  = lid >> 4;
    const int u   = 8 * w + lid4;                /* this thread's hidden unit */

    /* ---- A fragments of W_hh, loaded ONCE from global (64 regs) ---- */
    uint32_t A[2][8][4];
    #pragma unroll
    for (int mt = 0; mt < 2; mt++)
        #pragma unroll
        for (int kb = 0; kb < 8; kb++) {
            const unsigned short* r0 = &d_W16[((2 * mt)     * 128 + u) * 128 + kb * 16 + 2 * lm4];
            const unsigned short* r1 = &d_W16[((2 * mt + 1) * 128 + u) * 128 + kb * 16 + 2 * lm4];
            A[mt][kb][0] = *(const uint32_t*)r0;
            A[mt][kb][1] = *(const uint32_t*)r1;
            A[mt][kb][2] = *(const uint32_t*)(r0 + 8);
            A[mt][kb][3] = *(const uint32_t*)(r1 + 8);
        }

    float u4[4], v4[4];
    #pragma unroll
    for (int b = 0; b < 4; b++) { u4[b] = d_u[b * 128 + u]; v4[b] = d_v[b * 128 + u]; }

    float cst[8];
    #pragma unroll
    for (int i = 0; i < 8; i++) cst[i] = 0.0f;

    /* zero read buffer 0 */
    for (int p = tid; p < 2560; p += THR) ((uint32_t*)shh[0])[p] = 0u;
    __syncthreads();

    const uint32_t sb_h = smem_u32(shh);
    const uint32_t hLane = (uint32_t)rl * 80 + (uint32_t)ch * 16;
    const int gab = blockIdx.x * 32;

    for (int step = 0; step < LN; step++) {
        const uint32_t hRd = sb_h + (uint32_t)(step & 1) * 10240 + hLane;
        unsigned short* hw = shh[(step & 1) ^ 1];

        /* x prefetch: latency hides under the MMA phases */
        float2 xv[4];
        {
            const float2* xp = (const float2*)&d_Xt[step * KN + gab];
            #pragma unroll
            for (int nt = 0; nt < 4; nt++) xv[nt] = __ldg(&xp[nt * 4 + lm4]);
        }

        float acc[2][4][4];
        #pragma unroll
        for (int mt = 0; mt < 2; mt++)
            #pragma unroll
            for (int nt = 0; nt < 4; nt++)
                #pragma unroll
                for (int q = 0; q < 4; q++) acc[mt][nt][q] = 0.0f;

        /* phase A: arrays 0-15 (nt 0,1) */
        #pragma unroll
        for (int kb = 0; kb < 8; kb++) {
            uint32_t q0, q1, q2, q3;
            ldsm4t(q0, q1, q2, q3, hRd + (uint32_t)kb * 1280);
            uint32_t B0[2] = {q0, q1}, B1[2] = {q2, q3};
            mma_(acc[0][0], A[0][kb], B0);
            mma_(acc[1][0], A[1][kb], B0);
            mma_(acc[0][1], A[0][kb], B1);
            mma_(acc[1][1], A[1][kb], B1);
        }
        /* phase B: arrays 16-31 (nt 2,3) */
        #pragma unroll
        for (int kb = 0; kb < 8; kb++) {
            uint32_t q0, q1, q2, q3;
            ldsm4t(q0, q1, q2, q3, hRd + (uint32_t)kb * 1280 + 32);
            uint32_t B2[2] = {q0, q1}, B3[2] = {q2, q3};
            mma_(acc[0][2], A[0][kb], B2);
            mma_(acc[1][2], A[1][kb], B2);
            mma_(acc[0][3], A[0][kb], B3);
            mma_(acc[1][3], A[1][kb], B3);
        }

        /* epilogue: nt 0,1 only wait on phase-A accs -> overlap with phase-B tensor */
        #pragma unroll
        for (int nt = 0; nt < 4; nt++) {
            float hv[2];
            #pragma unroll
            for (int q = 0; q < 2; q++) {
                float x  = q ? xv[nt].y : xv[nt].x;
                float gi = acc[0][nt][q]     + fmaf(u4[0], x, v4[0]);
                float gf = acc[0][nt][2 + q] + fmaf(u4[1], x, v4[1]);
                float gg = acc[1][nt][q]     + fmaf(u4[2], x, v4[2]);
                float go = acc[1][nt][2 + q] + fmaf(u4[3], x, v4[3]);
                float c2 = siga(gf) * cst[nt * 2 + q] + siga(gi) * tanha(gg);
                float h  = siga(go) * tanha(c2);
                cst[nt * 2 + q] = c2;
                hv[q] = h;
            }
            *(unsigned*)&hw[u * 40 + nt * 8 + 2 * lm4] = f16x2pk(hv[0], hv[1]);
        }
        __syncthreads();
    }

    /* ---- stage c to smem for the f-gate pass ---- */
    #pragma unroll
    for (int nt = 0; nt < 4; nt++) {
        shc[u * 33 + nt * 8 + 2 * lm4]     = cst[nt * 2 + 0];
        shc[u * 33 + nt * 8 + 2 * lm4 + 1] = cst[nt * 2 + 1];
    }
    __syncthreads();

    /* ---- f-gate GEMM: warp w -> m16 tile (w&7), n-half (w>>3) ---- */
    const int mt = w & 7, nh = w >> 3;
    uint32_t Af[8][4];
    #pragma unroll
    for (int kb = 0; kb < 8; kb++) {
        const unsigned short* r0 = &d_Wf16[(16 * mt + lid4) * 128 + kb * 16 + 2 * lm4];
        const unsigned short* r1 = r0 + 8 * 128;
        Af[kb][0] = *(const uint32_t*)r0;
        Af[kb][1] = *(const uint32_t*)r1;
        Af[kb][2] = *(const uint32_t*)(r0 + 8);
        Af[kb][3] = *(const uint32_t*)(r1 + 8);
    }
    float fa[2][4];
    #pragma unroll
    for (int nt = 0; nt < 2; nt++)
        #pragma unroll
        for (int q = 0; q < 4; q++) fa[nt][q] = 0.0f;
    const uint32_t hF = sb_h + hLane + (uint32_t)nh * 32;   /* final h is in buffer 0 */
    #pragma unroll
    for (int kb = 0; kb < 8; kb++) {
        uint32_t q0, q1, q2, q3;
        ldsm4t(q0, q1, q2, q3, hF + (uint32_t)kb * 1280);
        uint32_t B0[2] = {q0, q1}, B1[2] = {q2, q3};
        mma_(fa[0], Af[kb], B0);
        mma_(fa[1], Af[kb], B1);
    }
    const int r0 = 16 * mt + lid4, r1 = r0 + 8;
    float b0 = bfh[r0], b1 = bfh[r1];
    float f0 = 0.0f, f1 = 0.0f;
    #pragma unroll
    for (int nt = 0; nt < 2; nt++)
        #pragma unroll
        for (int q = 0; q < 2; q++) {
            int col = nh * 16 + nt * 8 + 2 * lm4 + q;
            f0 += sigf(fa[nt][q]     + b0) * shc[r0 * 33 + col];
            f1 += sigf(fa[nt][2 + q] + b1) * shc[r1 * 33 + col];
        }
    f0 += __shfl_xor_sync(0xFFFFFFFFu, f0, 1);
    f0 += __shfl_xor_sync(0xFFFFFFFFu, f0, 2);
    f1 += __shfl_xor_sync(0xFFFFFFFFu, f1, 1);
    f1 += __shfl_xor_sync(0xFFFFFFFFu, f1, 2);
    if (lm4 == 0) { shred[nh][r0] = f0; shred[nh][r1] = f1; }
    __syncthreads();

    if (tid < 128) {
        float fc = shred[0][tid] + shred[1][tid];
        float hs = 0.0f;
        #pragma unroll 8
        for (int a = 0; a < 32; a++) hs += f16tof(shh[0][tid * 40 + a]);
        d_fcp[blockIdx.x * MEM + tid] = fc;
        d_hsp[blockIdx.x * MEM + tid] = hs;
    }
}

/* -------- 5) final tree-LSTM root math -------- */
__global__ void k_final(const float* __restrict__ Wiou, const float* __restrict__ biou,
                        const float* __restrict__ Wlout, const float* __restrict__ blout,
                        float* __restrict__ out) {
    __shared__ float sh_hs[128];
    __shared__ float sh_h[128];
    int k = threadIdx.x;
    float fc = 0.0f, hs = 0.0f;
    for (int b = 0; b < NBLK; b++) {
        fc += d_fcp[b * MEM + k];
        hs += d_hsp[b * MEM + k];
    }
    sh_hs[k] = hs;
    __syncthreads();
    float iv = biou[k], ov = biou[128 + k], uv = biou[256 + k];
    #pragma unroll 8
    for (int j = 0; j < 128; j++) {
        float h = sh_hs[j];
        iv += Wiou[k * 128 + j] * h;
        ov += Wiou[(128 + k) * 128 + j] * h;
        uv += Wiou[(256 + k) * 128 + j] * h;
    }
    float cv = sigf(iv) * tanh_(uv) + fc;
    float hv = sigf(ov) * tanh_(cv);
    out[k]  = cv;
    sh_h[k] = hv;
    __syncthreads();
    float acc = blout[k];
    #pragma unroll 8
    for (int j = 0; j < 128; j++) acc += Wlout[k * 128 + j] * sh_h[j];
    out[128 + k] = acc;
}

extern "C" void kernel_launch(void* const* d_in, const int* in_sizes, int n_in,
                              void* d_out, int out_size) {
    const float* numbers = (const float*)d_in[0];
    const float* wnum    = (const float*)d_in[1];
    const float* bnum    = (const float*)d_in[2];
    const float* Wih     = (const float*)d_in[3];
    const float* Whh     = (const float*)d_in[4];
    const float* bih     = (const float*)d_in[5];
    const float* bhh     = (const float*)d_in[6];
    const float* Wfh     = (const float*)d_in[7];
    const float* bfh     = (const float*)d_in[8];
    const float* Wiou    = (const float*)d_in[9];
    const float* biou    = (const float*)d_in[10];
    const float* Wlout   = (const float*)d_in[11];
    const float* blout   = (const float*)d_in[12];
    float* out = (float*)d_out;

    k_stats<<<1, 128>>>(numbers);
    k_norm<<<(KN * LN + 255) / 256, 256>>>(numbers);
    k_prep<<<(G4 * MEM + MEM * MEM + G4 + 255) / 256, 256>>>(Wih, Whh, bih, bhh, Wfh, wnum, bnum);
    k_lstm<<<NBLK, THR>>>(bfh);
    k_final<<<1, 128>>>(Wiou, biou, Wlout, blout, out);
}